// round 1
// baseline (speedup 1.0000x reference)
#include <cuda_runtime.h>
#include <cuda_bf16.h>
#include <math.h>

// ---------------------------------------------------------------------------
// Problem constants
// ---------------------------------------------------------------------------
#define B_     2
#define SQ_    2048
#define H_     4096
#define NH_    32
#define HD_    128
#define NG_    2
#define QKV_OUT_ (NH_*HD_ + 2*NG_*HD_)   // 4608
#define Q_SZ_    (NH_*HD_)               // 4096
#define KV_SZ_   (NG_*HD_)               // 256
#define REP_     (NH_/NG_)               // 16

// ---------------------------------------------------------------------------
// Scratch (static __device__ globals: no allocation in kernel_launch)
// ---------------------------------------------------------------------------
__device__ float g_mixed[(size_t)B_*SQ_*QKV_OUT_];        // 75.5 MB
__device__ float g_q[(size_t)B_*NH_*SQ_*HD_];             // 64 MB
__device__ float g_k[(size_t)B_*NG_*SQ_*HD_];             // 4 MB
__device__ float g_v[(size_t)B_*NG_*SQ_*HD_];             // 4 MB
__device__ float g_ctx[(size_t)B_*SQ_*H_];                // 64 MB

// ---------------------------------------------------------------------------
// SGEMM: C[M,N] = A[M,K] @ B[K,N] (+ bias).  BM=BN=128, BK=8, 256 thr, 8x8/thr
// M,N,K all divisible by tile sizes for both calls (4096x4608x4096, 4096^3).
// ---------------------------------------------------------------------------
template<bool HAS_BIAS>
__global__ __launch_bounds__(256)
void sgemm_kernel(const float* __restrict__ A, const float* __restrict__ Bm,
                  const float* __restrict__ bias, float* __restrict__ C,
                  int M, int N, int K)
{
    constexpr int BM = 128, BN = 128, BK = 8;
    __shared__ float As[BK][BM];
    __shared__ float Bs[BK][BN];

    const int tid = threadIdx.x;
    const int tx  = tid & 15;        // 0..15 -> 8 cols each
    const int ty  = tid >> 4;        // 0..15 -> 8 rows each
    const int m0  = blockIdx.y * BM;
    const int n0  = blockIdx.x * BN;

    const int arow = tid >> 1;             // 0..127
    const int acol = (tid & 1) * 4;        // 0 or 4
    const int brow = tid >> 5;             // 0..7
    const int bcol = (tid & 31) * 4;       // 0..124

    float acc[8][8];
    #pragma unroll
    for (int i = 0; i < 8; i++)
        #pragma unroll
        for (int j = 0; j < 8; j++) acc[i][j] = 0.f;

    // prefetch first slab
    float4 aReg = *(const float4*)&A[(size_t)(m0 + arow) * K + acol];
    float4 bReg = *(const float4*)&Bm[(size_t)brow * N + n0 + bcol];

    for (int k0 = 0; k0 < K; k0 += BK) {
        // commit prefetched slab to smem (A transposed)
        As[acol + 0][arow] = aReg.x;
        As[acol + 1][arow] = aReg.y;
        As[acol + 2][arow] = aReg.z;
        As[acol + 3][arow] = aReg.w;
        *(float4*)&Bs[brow][bcol] = bReg;
        __syncthreads();

        // prefetch next slab while computing
        if (k0 + BK < K) {
            aReg = *(const float4*)&A[(size_t)(m0 + arow) * K + (k0 + BK) + acol];
            bReg = *(const float4*)&Bm[(size_t)(k0 + BK + brow) * N + n0 + bcol];
        }

        #pragma unroll
        for (int k = 0; k < BK; k++) {
            float ar[8], br[8];
            *(float4*)&ar[0] = *(float4*)&As[k][ty * 8];
            *(float4*)&ar[4] = *(float4*)&As[k][ty * 8 + 4];
            *(float4*)&br[0] = *(float4*)&Bs[k][tx * 8];
            *(float4*)&br[4] = *(float4*)&Bs[k][tx * 8 + 4];
            #pragma unroll
            for (int i = 0; i < 8; i++)
                #pragma unroll
                for (int j = 0; j < 8; j++)
                    acc[i][j] = fmaf(ar[i], br[j], acc[i][j]);
        }
        __syncthreads();
    }

    // epilogue
    float bv[8];
    if (HAS_BIAS) {
        *(float4*)&bv[0] = *(const float4*)&bias[n0 + tx * 8];
        *(float4*)&bv[4] = *(const float4*)&bias[n0 + tx * 8 + 4];
    }
    #pragma unroll
    for (int i = 0; i < 8; i++) {
        const size_t row = (size_t)(m0 + ty * 8 + i);
        float* cp = &C[row * N + n0 + tx * 8];
        float4 r0, r1;
        if (HAS_BIAS) {
            r0 = make_float4(acc[i][0]+bv[0], acc[i][1]+bv[1], acc[i][2]+bv[2], acc[i][3]+bv[3]);
            r1 = make_float4(acc[i][4]+bv[4], acc[i][5]+bv[5], acc[i][6]+bv[6], acc[i][7]+bv[7]);
        } else {
            r0 = make_float4(acc[i][0], acc[i][1], acc[i][2], acc[i][3]);
            r1 = make_float4(acc[i][4], acc[i][5], acc[i][6], acc[i][7]);
        }
        *(float4*)&cp[0] = r0;
        *(float4*)&cp[4] = r1;
    }
}

// ---------------------------------------------------------------------------
// RoPE + scatter:  mixed[b,s,:] -> q[b,h,s,:], k[b,g,s,:], v[b,g,s,:]
// rot_dim = 64 (first 32 pairs), dims 64..127 pass through.
// grid: (NH + 2*NG, SQ, B), block: 128
// ---------------------------------------------------------------------------
__global__ __launch_bounds__(128)
void rope_scatter_kernel(const float* __restrict__ mixed,
                         const float* __restrict__ cache,
                         float* __restrict__ q, float* __restrict__ k,
                         float* __restrict__ v)
{
    const int head = blockIdx.x;        // 0..35
    const int s    = blockIdx.y;
    const int b    = blockIdx.z;
    const int j    = threadIdx.x;       // 0..127

    const float* row = mixed + ((size_t)(b * SQ_ + s)) * QKV_OUT_;

    if (head < NH_ + NG_) {
        // q or k head: apply RoPE
        const float* x = (head < NH_) ? (row + head * HD_)
                                      : (row + Q_SZ_ + (head - NH_) * HD_);
        float out;
        if (j < 64) {
            const int p = j >> 1;
            const float x0 = x[2 * p], x1 = x[2 * p + 1];
            const float c0 = cache[((size_t)s * 32 + p) * 2 + 0];
            const float c1 = cache[((size_t)s * 32 + p) * 2 + 1];
            out = (j & 1) ? fmaf(x1, c0, x0 * c1) : fmaf(x0, c0, -x1 * c1);
        } else {
            out = x[j];
        }
        float* dst = (head < NH_)
            ? &q[(((size_t)b * NH_ + head) * SQ_ + s) * HD_]
            : &k[(((size_t)b * NG_ + (head - NH_)) * SQ_ + s) * HD_];
        dst[j] = out;
    } else {
        const int g = head - NH_ - NG_;
        v[(((size_t)b * NG_ + g) * SQ_ + s) * HD_ + j] =
            row[Q_SZ_ + KV_SZ_ + g * HD_ + j];
    }
}

// ---------------------------------------------------------------------------
// fp32 flash attention, causal, GQA (16 q-heads per kv-head).
// CTA: 64 q-rows x full HD. Tiles of 64 k-cols. 256 threads (16x16).
// S: each thread 4x4 of 64x64. O: each thread 4 rows x 8 cols of 64x128.
// Smem: Qs[T] 128x64, KVs (Kᵀ 128x64 then V 64x128), Ps 64x65.
// ---------------------------------------------------------------------------
#define FL_BM 64
#define FL_BN 64
#define FLASH_SMEM_BYTES ((FL_BM*HD_*2 + FL_BM*(FL_BN+1)) * 4)   // 82176

__device__ __forceinline__ float rowmax16(float x) {
    #pragma unroll
    for (int off = 1; off < 16; off <<= 1)
        x = fmaxf(x, __shfl_xor_sync(0xffffffffu, x, off));
    return x;
}
__device__ __forceinline__ float rowsum16(float x) {
    #pragma unroll
    for (int off = 1; off < 16; off <<= 1)
        x += __shfl_xor_sync(0xffffffffu, x, off);
    return x;
}

__global__ __launch_bounds__(256)
void flash_kernel(const float* __restrict__ q, const float* __restrict__ k,
                  const float* __restrict__ v, float* __restrict__ ctx)
{
    extern __shared__ float sm[];
    float* Qs  = sm;                     // [HD][FL_BM] transposed
    float* KVs = sm + HD_ * FL_BM;       // Kᵀ [HD][FL_BN]  /  V [FL_BN][HD]
    float* Ps  = sm + 2 * HD_ * FL_BM;   // [FL_BM][FL_BN+1]

    const int qb = blockIdx.x;
    const int h  = blockIdx.y;
    const int b  = blockIdx.z;
    const int g  = h / REP_;

    const int tid = threadIdx.x;
    const int tx  = tid & 15;
    const int ty  = tid >> 4;
    const int q0  = qb * FL_BM;

    const float* Qg = q + ((size_t)b * NH_ + h) * SQ_ * HD_;
    const float* Kg = k + ((size_t)b * NG_ + g) * SQ_ * HD_;
    const float* Vg = v + ((size_t)b * NG_ + g) * SQ_ * HD_;

    const float scale = 0.08838834764831845f;   // 1/sqrt(128)

    // load Q tile transposed, pre-scaled
    for (int it = tid; it < FL_BM * (HD_ / 4); it += 256) {
        const int r  = it >> 5;            // 0..63
        const int c4 = (it & 31) << 2;     // 0..124
        float4 t = *(const float4*)&Qg[(size_t)(q0 + r) * HD_ + c4];
        Qs[(c4 + 0) * FL_BM + r] = t.x * scale;
        Qs[(c4 + 1) * FL_BM + r] = t.y * scale;
        Qs[(c4 + 2) * FL_BM + r] = t.z * scale;
        Qs[(c4 + 3) * FL_BM + r] = t.w * scale;
    }

    float m[4], l[4], O[4][8];
    #pragma unroll
    for (int r = 0; r < 4; r++) {
        m[r] = -1e30f; l[r] = 0.f;
        #pragma unroll
        for (int c = 0; c < 8; c++) O[r][c] = 0.f;
    }

    const int jmax = qb;
    for (int j = 0; j <= jmax; j++) {
        const int k0 = j * FL_BN;
        __syncthreads();   // previous PV done (and Q load done on j==0)

        // load Kᵀ tile
        for (int it = tid; it < FL_BN * (HD_ / 4); it += 256) {
            const int r  = it >> 5;
            const int c4 = (it & 31) << 2;
            float4 t = *(const float4*)&Kg[(size_t)(k0 + r) * HD_ + c4];
            KVs[(c4 + 0) * FL_BN + r] = t.x;
            KVs[(c4 + 1) * FL_BN + r] = t.y;
            KVs[(c4 + 2) * FL_BN + r] = t.z;
            KVs[(c4 + 3) * FL_BN + r] = t.w;
        }
        __syncthreads();

        // S = Q @ Kᵀ  (4x4 per thread)
        float acc[4][4];
        #pragma unroll
        for (int r = 0; r < 4; r++)
            #pragma unroll
            for (int c = 0; c < 4; c++) acc[r][c] = 0.f;

        #pragma unroll 4
        for (int d = 0; d < HD_; d++) {
            float4 qa = *(float4*)&Qs[d * FL_BM + ty * 4];
            float4 kb = *(float4*)&KVs[d * FL_BN + tx * 4];
            float qr[4] = {qa.x, qa.y, qa.z, qa.w};
            float kr[4] = {kb.x, kb.y, kb.z, kb.w};
            #pragma unroll
            for (int r = 0; r < 4; r++)
                #pragma unroll
                for (int c = 0; c < 4; c++)
                    acc[r][c] = fmaf(qr[r], kr[c], acc[r][c]);
        }
        __syncthreads();   // done reading K

        // load V tile (natural layout) into same buffer
        for (int it = tid; it < FL_BN * (HD_ / 4); it += 256) {
            const int r  = it >> 5;
            const int c4 = (it & 31) << 2;
            *(float4*)&KVs[r * HD_ + c4] =
                *(const float4*)&Vg[(size_t)(k0 + r) * HD_ + c4];
        }

        // causal mask on diagonal tile
        if (j == jmax) {
            #pragma unroll
            for (int r = 0; r < 4; r++)
                #pragma unroll
                for (int c = 0; c < 4; c++)
                    if (k0 + tx * 4 + c > q0 + ty * 4 + r) acc[r][c] = -1e30f;
        }

        // online softmax update (all in registers; smem not touched)
        float p[4][4];
        #pragma unroll
        for (int r = 0; r < 4; r++) {
            float mt = fmaxf(fmaxf(acc[r][0], acc[r][1]),
                             fmaxf(acc[r][2], acc[r][3]));
            mt = rowmax16(mt);
            const float mn = fmaxf(m[r], mt);
            const float alpha = __expf(m[r] - mn);
            m[r] = mn;
            float ls = 0.f;
            #pragma unroll
            for (int c = 0; c < 4; c++) {
                p[r][c] = __expf(acc[r][c] - mn);
                ls += p[r][c];
            }
            ls = rowsum16(ls);
            l[r] = l[r] * alpha + ls;
            #pragma unroll
            for (int c = 0; c < 8; c++) O[r][c] *= alpha;
        }

        // stage P
        #pragma unroll
        for (int r = 0; r < 4; r++)
            #pragma unroll
            for (int c = 0; c < 4; c++)
                Ps[(ty * 4 + r) * (FL_BN + 1) + tx * 4 + c] = p[r][c];
        __syncthreads();   // Ps visible, V loaded

        // O += P @ V
        #pragma unroll 2
        for (int kk = 0; kk < FL_BN; kk++) {
            float pr[4];
            #pragma unroll
            for (int r = 0; r < 4; r++)
                pr[r] = Ps[(ty * 4 + r) * (FL_BN + 1) + kk];
            float4 v0 = *(float4*)&KVs[kk * HD_ + tx * 8];
            float4 v1 = *(float4*)&KVs[kk * HD_ + tx * 8 + 4];
            float vr[8] = {v0.x, v0.y, v0.z, v0.w, v1.x, v1.y, v1.z, v1.w};
            #pragma unroll
            for (int r = 0; r < 4; r++)
                #pragma unroll
                for (int c = 0; c < 8; c++)
                    O[r][c] = fmaf(pr[r], vr[c], O[r][c]);
        }
    }

    // epilogue: normalize and store to ctx[b, s, h*HD + d]
    #pragma unroll
    for (int r = 0; r < 4; r++) {
        const float inv = 1.f / l[r];
        const int row = q0 + ty * 4 + r;
        float* cp = &ctx[((size_t)(b * SQ_ + row)) * H_ + h * HD_ + tx * 8];
        float4 o0 = make_float4(O[r][0]*inv, O[r][1]*inv, O[r][2]*inv, O[r][3]*inv);
        float4 o1 = make_float4(O[r][4]*inv, O[r][5]*inv, O[r][6]*inv, O[r][7]*inv);
        *(float4*)&cp[0] = o0;
        *(float4*)&cp[4] = o1;
    }
}

// ---------------------------------------------------------------------------
// Launch
// ---------------------------------------------------------------------------
extern "C" void kernel_launch(void* const* d_in, const int* in_sizes, int n_in,
                              void* d_out, int out_size)
{
    const float* hidden = (const float*)d_in[0];   // [2,2048,4096]
    const float* rope   = (const float*)d_in[1];   // [1,2048,32,2]
    const float* Wqkv   = (const float*)d_in[2];   // [4096,4608]
    const float* bqkv   = (const float*)d_in[3];   // [4608]
    const float* Wd     = (const float*)d_in[4];   // [4096,4096]
    float* out = (float*)d_out;                    // [2,2048,4096]

    float *mixed, *qp, *kp, *vp, *ctx;
    cudaGetSymbolAddress((void**)&mixed, g_mixed);
    cudaGetSymbolAddress((void**)&qp,    g_q);
    cudaGetSymbolAddress((void**)&kp,    g_k);
    cudaGetSymbolAddress((void**)&vp,    g_v);
    cudaGetSymbolAddress((void**)&ctx,   g_ctx);

    const int M = B_ * SQ_;   // 4096

    // 1) mixed = hidden @ W_qkv + b_qkv
    sgemm_kernel<true><<<dim3(QKV_OUT_ / 128, M / 128), 256>>>(
        hidden, Wqkv, bqkv, mixed, M, QKV_OUT_, H_);

    // 2) RoPE + scatter into q/k/v layouts
    rope_scatter_kernel<<<dim3(NH_ + 2 * NG_, SQ_, B_), 128>>>(
        mixed, rope, qp, kp, vp);

    // 3) causal GQA flash attention
    cudaFuncSetAttribute(flash_kernel,
                         cudaFuncAttributeMaxDynamicSharedMemorySize,
                         FLASH_SMEM_BYTES);
    flash_kernel<<<dim3(SQ_ / FL_BM, NH_, B_), 256, FLASH_SMEM_BYTES>>>(
        qp, kp, vp, ctx);

    // 4) out = ctx @ W_dense
    sgemm_kernel<false><<<dim3(H_ / 128, M / 128), 256>>>(
        ctx, Wd, nullptr, out, M, H_, H_);
}

// round 3
// speedup vs baseline: 1.4690x; 1.4690x over previous
#include <cuda_runtime.h>
#include <cuda_bf16.h>
#include <cstdint>
#include <math.h>

// ---------------------------------------------------------------------------
// Problem constants
// ---------------------------------------------------------------------------
#define B_     2
#define SQ_    2048
#define H_     4096
#define NH_    32
#define HD_    128
#define NG_    2
#define QKV_OUT_ (NH_*HD_ + 2*NG_*HD_)   // 4608
#define Q_SZ_    (NH_*HD_)               // 4096
#define KV_SZ_   (NG_*HD_)               // 256
#define REP_     (NH_/NG_)               // 16
#define MM_      (B_*SQ_)                // 4096
#define KSPLIT_  (3*H_)                  // 12288 (K' for split GEMM)

// ---------------------------------------------------------------------------
// Scratch (static __device__ globals: no allocation in kernel_launch)
// ---------------------------------------------------------------------------
__device__ float g_mixed[(size_t)MM_*QKV_OUT_];
__device__ float g_q[(size_t)B_*NH_*SQ_*HD_];
__device__ float g_k[(size_t)B_*NG_*SQ_*HD_];
__device__ float g_v[(size_t)B_*NG_*SQ_*HD_];
__device__ float g_ctx[(size_t)MM_*H_];
// K-concatenated split operands: A' = [Ah | Al | Ah], B'^T = [Bh | Bh | Bl]
__device__ __nv_bfloat16 g_as[(size_t)MM_*KSPLIT_];        // 100.7 MB
__device__ __nv_bfloat16 g_bs[(size_t)QKV_OUT_*KSPLIT_];   // 113 MB

// ---------------------------------------------------------------------------
// Helpers
// ---------------------------------------------------------------------------
__device__ __forceinline__ uint32_t smem_u32(const void* p) {
    uint32_t a;
    asm("{ .reg .u64 t; cvta.to.shared.u64 t, %1; cvt.u32.u64 %0, t; }" : "=r"(a) : "l"(p));
    return a;
}
__device__ __forceinline__ void cp_async16(uint32_t dst, const void* src) {
    asm volatile("cp.async.cg.shared.global [%0], [%1], 16;" :: "r"(dst), "l"(src));
}
__device__ __forceinline__ void cp_commit() {
    asm volatile("cp.async.commit_group;");
}
template<int N>
__device__ __forceinline__ void cp_wait() {
    asm volatile("cp.async.wait_group %0;" :: "n"(N));
}
__device__ __forceinline__ void ldm_x4(uint32_t& r0, uint32_t& r1, uint32_t& r2,
                                       uint32_t& r3, uint32_t addr) {
    asm volatile("ldmatrix.sync.aligned.m8n8.x4.shared.b16 {%0,%1,%2,%3}, [%4];"
                 : "=r"(r0), "=r"(r1), "=r"(r2), "=r"(r3) : "r"(addr));
}
__device__ __forceinline__ void mma_bf16(float* d, const uint32_t* a,
                                         uint32_t b0, uint32_t b1) {
    asm volatile(
        "mma.sync.aligned.m16n8k16.row.col.f32.bf16.bf16.f32 "
        "{%0,%1,%2,%3}, {%4,%5,%6,%7}, {%8,%9}, {%0,%1,%2,%3};"
        : "+f"(d[0]), "+f"(d[1]), "+f"(d[2]), "+f"(d[3])
        : "r"(a[0]), "r"(a[1]), "r"(a[2]), "r"(a[3]), "r"(b0), "r"(b1));
}

// ---------------------------------------------------------------------------
// Split kernels: fp32 -> bf16 hi/lo, K-concatenated
// ---------------------------------------------------------------------------
// A[M,K] fp32 -> As[M, 3K] bf16 with segments [hi | lo | hi]
__global__ __launch_bounds__(256)
void split_a_kernel(const float* __restrict__ A, __nv_bfloat16* __restrict__ As,
                    int K, size_t n8)
{
    size_t g = (size_t)blockIdx.x * 256 + threadIdx.x;
    if (g >= n8) return;
    const int kpr = K / 8;               // 8-elem chunks per row
    const size_t m  = g / kpr;
    const int   k8  = (int)(g % kpr) * 8;
    float4 a0 = *(const float4*)&A[m * K + k8];
    float4 a1 = *(const float4*)&A[m * K + k8 + 4];
    float v[8] = {a0.x,a0.y,a0.z,a0.w,a1.x,a1.y,a1.z,a1.w};
    __nv_bfloat162 h[4], l[4];
    #pragma unroll
    for (int j = 0; j < 4; j++) {
        __nv_bfloat16 h0 = __float2bfloat16(v[2*j]);
        __nv_bfloat16 h1 = __float2bfloat16(v[2*j+1]);
        h[j] = __nv_bfloat162(h0, h1);
        l[j] = __nv_bfloat162(__float2bfloat16(v[2*j]   - __bfloat162float(h0)),
                              __float2bfloat16(v[2*j+1] - __bfloat162float(h1)));
    }
    __nv_bfloat16* row = As + m * (size_t)(3*K);
    *(uint4*)&row[k8]         = *(uint4*)h;
    *(uint4*)&row[K + k8]     = *(uint4*)l;
    *(uint4*)&row[2*K + k8]   = *(uint4*)h;
}

// W[K,N] fp32 -> Bs[N, 3K] bf16 (transposed) with segments [hi | hi | lo]
__global__ __launch_bounds__(256)
void transpose_split_kernel(const float* __restrict__ W, __nv_bfloat16* __restrict__ Bs,
                            int K, int N)
{
    __shared__ float t[32][33];
    const int n0 = blockIdx.x * 32, k0 = blockIdx.y * 32;
    const int tx = threadIdx.x & 31, ty = threadIdx.x >> 5;
    #pragma unroll
    for (int i = 0; i < 4; i++)
        t[ty + 8*i][tx] = W[(size_t)(k0 + ty + 8*i) * N + n0 + tx];
    __syncthreads();
    #pragma unroll
    for (int i = 0; i < 4; i++) {
        float v = t[tx][ty + 8*i];
        __nv_bfloat16 h = __float2bfloat16(v);
        __nv_bfloat16 l = __float2bfloat16(v - __bfloat162float(h));
        __nv_bfloat16* row = Bs + (size_t)(n0 + ty + 8*i) * (3*K);
        row[k0 + tx]         = h;
        row[K + k0 + tx]     = h;
        row[2*K + k0 + tx]   = l;
    }
}

// ---------------------------------------------------------------------------
// bf16 tensor-core GEMM (mma.sync m16n8k16): C[M,N] = As[M,K'] @ Bs[N,K']^T
// BM=BN=128, BK=32, 8 warps (2x4), 3-stage cp.async pipeline.
// Smem rows padded to 40 bf16 (80B) for conflict-free ldmatrix.
// ---------------------------------------------------------------------------
#define GBM 128
#define GBN 128
#define GBK 32
#define GLD 40                                // padded leading dim (bf16)
#define STG_A_BYTES (GBM*GLD*2)               // 10240
#define STG_BYTES   ((GBM+GBN)*GLD*2)         // 20480
#define GSTAGES 3
#define GEMM_SMEM_BYTES (GSTAGES*STG_BYTES)   // 61440

__global__ __launch_bounds__(256)
void mma_gemm_kernel(const __nv_bfloat16* __restrict__ Ag,
                     const __nv_bfloat16* __restrict__ Bg,
                     const float* __restrict__ bias, float* __restrict__ C,
                     int N, int Kp)
{
    extern __shared__ char dsm[];
    const uint32_t sbase = smem_u32(dsm);

    const int tid  = threadIdx.x;
    const int lane = tid & 31;
    const int wid  = tid >> 5;
    const int wm   = wid >> 2;          // 0..1
    const int wn   = wid & 3;           // 0..3
    const int m0   = blockIdx.y * GBM;
    const int n0   = blockIdx.x * GBN;

    const __nv_bfloat16* Arow = Ag + (size_t)m0 * Kp;
    const __nv_bfloat16* Brow = Bg + (size_t)n0 * Kp;

    const int NIT = Kp / GBK;

    // per-thread cp.async source precompute: thread covers granules tid, tid+256
    // granule g: r = g>>2 (row 0..127), c = g&3 (16B col)
    auto issue_stage = [&](int kt, int slot) {
        const uint32_t sa = sbase + slot * STG_BYTES;
        const uint32_t sb = sa + STG_A_BYTES;
        const int kO = kt * GBK;
        #pragma unroll
        for (int h = 0; h < 2; h++) {
            const int g = tid + h * 256;
            const int r = g >> 2, c = g & 3;
            cp_async16(sa + (r * GLD + c * 8) * 2,
                       Arow + (size_t)r * Kp + kO + c * 8);
            cp_async16(sb + (r * GLD + c * 8) * 2,
                       Brow + (size_t)r * Kp + kO + c * 8);
        }
        cp_commit();
    };

    float acc[4][4][4];
    #pragma unroll
    for (int i = 0; i < 4; i++)
        #pragma unroll
        for (int j = 0; j < 4; j++)
            #pragma unroll
            for (int r = 0; r < 4; r++) acc[i][j][r] = 0.f;

    issue_stage(0, 0);
    issue_stage(1, 1);

    // ldmatrix lane addressing (precompute per-thread row/col offsets)
    const int a_r = lane & 15;              // row within m16
    const int a_c = (lane >> 4) << 3;       // 0 or 8 (k)
    const int b_r = (lane & 7) + ((lane >> 4) << 3);   // n offset 0..15
    const int b_c = ((lane >> 3) & 1) << 3;            // 0 or 8 (k)

    for (int kt = 0; kt < NIT; kt++) {
        cp_wait<1>();
        __syncthreads();
        if (kt + 2 < NIT) issue_stage(kt + 2, (kt + 2) % GSTAGES);
        else cp_commit();   // keep group-count invariant

        const int slot = kt % GSTAGES;
        const uint32_t sa = sbase + slot * STG_BYTES;
        const uint32_t sb = sa + STG_A_BYTES;

        #pragma unroll
        for (int ks = 0; ks < 2; ks++) {
            const int kb = ks * 16;
            uint32_t a[4][4];
            #pragma unroll
            for (int i = 0; i < 4; i++)
                ldm_x4(a[i][0], a[i][1], a[i][2], a[i][3],
                       sa + ((wm*64 + i*16 + a_r) * GLD + kb + a_c) * 2);
            uint32_t b[4][2];
            #pragma unroll
            for (int j = 0; j < 2; j++) {
                uint32_t r0, r1, r2, r3;
                ldm_x4(r0, r1, r2, r3,
                       sb + ((wn*32 + j*16 + b_r) * GLD + kb + b_c) * 2);
                b[j*2][0]   = r0; b[j*2][1]   = r1;
                b[j*2+1][0] = r2; b[j*2+1][1] = r3;
            }
            #pragma unroll
            for (int i = 0; i < 4; i++)
                #pragma unroll
                for (int j = 0; j < 4; j++)
                    mma_bf16(acc[i][j], a[i], b[j][0], b[j][1]);
        }
        __syncthreads();
    }

    // epilogue: acc[i][j]: rows m0+wm*64+i*16+{lane>>2, +8}, cols n0+wn*32+j*8+(lane&3)*2
    const int cr = lane >> 2;
    const int cc = (lane & 3) * 2;
    #pragma unroll
    for (int j = 0; j < 4; j++) {
        const int col = n0 + wn*32 + j*8 + cc;
        float2 bv = make_float2(0.f, 0.f);
        if (bias) bv = *(const float2*)&bias[col];
        #pragma unroll
        for (int i = 0; i < 4; i++) {
            const int row = m0 + wm*64 + i*16 + cr;
            *(float2*)&C[(size_t)row * N + col] =
                make_float2(acc[i][j][0] + bv.x, acc[i][j][1] + bv.y);
            *(float2*)&C[(size_t)(row + 8) * N + col] =
                make_float2(acc[i][j][2] + bv.x, acc[i][j][3] + bv.y);
        }
    }
}

// ---------------------------------------------------------------------------
// RoPE + scatter (unchanged)
// ---------------------------------------------------------------------------
__global__ __launch_bounds__(128)
void rope_scatter_kernel(const float* __restrict__ mixed,
                         const float* __restrict__ cache,
                         float* __restrict__ q, float* __restrict__ k,
                         float* __restrict__ v)
{
    const int head = blockIdx.x;
    const int s    = blockIdx.y;
    const int b    = blockIdx.z;
    const int j    = threadIdx.x;

    const float* row = mixed + ((size_t)(b * SQ_ + s)) * QKV_OUT_;

    if (head < NH_ + NG_) {
        const float* x = (head < NH_) ? (row + head * HD_)
                                      : (row + Q_SZ_ + (head - NH_) * HD_);
        float out;
        if (j < 64) {
            const int p = j >> 1;
            const float x0 = x[2 * p], x1 = x[2 * p + 1];
            const float c0 = cache[((size_t)s * 32 + p) * 2 + 0];
            const float c1 = cache[((size_t)s * 32 + p) * 2 + 1];
            out = (j & 1) ? fmaf(x1, c0, x0 * c1) : fmaf(x0, c0, -x1 * c1);
        } else {
            out = x[j];
        }
        float* dst = (head < NH_)
            ? &q[(((size_t)b * NH_ + head) * SQ_ + s) * HD_]
            : &k[(((size_t)b * NG_ + (head - NH_)) * SQ_ + s) * HD_];
        dst[j] = out;
    } else {
        const int g = head - NH_ - NG_;
        v[(((size_t)b * NG_ + g) * SQ_ + s) * HD_ + j] =
            row[Q_SZ_ + KV_SZ_ + g * HD_ + j];
    }
}

// ---------------------------------------------------------------------------
// fp32 flash attention (unchanged from round 1)
// ---------------------------------------------------------------------------
#define FL_BM 64
#define FL_BN 64
#define FLASH_SMEM_BYTES ((FL_BM*HD_*2 + FL_BM*(FL_BN+1)) * 4)

__device__ __forceinline__ float rowmax16(float x) {
    #pragma unroll
    for (int off = 1; off < 16; off <<= 1)
        x = fmaxf(x, __shfl_xor_sync(0xffffffffu, x, off));
    return x;
}
__device__ __forceinline__ float rowsum16(float x) {
    #pragma unroll
    for (int off = 1; off < 16; off <<= 1)
        x += __shfl_xor_sync(0xffffffffu, x, off);
    return x;
}

__global__ __launch_bounds__(256)
void flash_kernel(const float* __restrict__ q, const float* __restrict__ k,
                  const float* __restrict__ v, float* __restrict__ ctx)
{
    extern __shared__ float sm[];
    float* Qs  = sm;
    float* KVs = sm + HD_ * FL_BM;
    float* Ps  = sm + 2 * HD_ * FL_BM;

    const int qb = blockIdx.x;
    const int h  = blockIdx.y;
    const int b  = blockIdx.z;
    const int g  = h / REP_;

    const int tid = threadIdx.x;
    const int tx  = tid & 15;
    const int ty  = tid >> 4;
    const int q0  = qb * FL_BM;

    const float* Qg = q + ((size_t)b * NH_ + h) * SQ_ * HD_;
    const float* Kg = k + ((size_t)b * NG_ + g) * SQ_ * HD_;
    const float* Vg = v + ((size_t)b * NG_ + g) * SQ_ * HD_;

    const float scale = 0.08838834764831845f;

    for (int it = tid; it < FL_BM * (HD_ / 4); it += 256) {
        const int r  = it >> 5;
        const int c4 = (it & 31) << 2;
        float4 t = *(const float4*)&Qg[(size_t)(q0 + r) * HD_ + c4];
        Qs[(c4 + 0) * FL_BM + r] = t.x * scale;
        Qs[(c4 + 1) * FL_BM + r] = t.y * scale;
        Qs[(c4 + 2) * FL_BM + r] = t.z * scale;
        Qs[(c4 + 3) * FL_BM + r] = t.w * scale;
    }

    float m[4], l[4], O[4][8];
    #pragma unroll
    for (int r = 0; r < 4; r++) {
        m[r] = -1e30f; l[r] = 0.f;
        #pragma unroll
        for (int c = 0; c < 8; c++) O[r][c] = 0.f;
    }

    const int jmax = qb;
    for (int j = 0; j <= jmax; j++) {
        const int k0 = j * FL_BN;
        __syncthreads();

        for (int it = tid; it < FL_BN * (HD_ / 4); it += 256) {
            const int r  = it >> 5;
            const int c4 = (it & 31) << 2;
            float4 t = *(const float4*)&Kg[(size_t)(k0 + r) * HD_ + c4];
            KVs[(c4 + 0) * FL_BN + r] = t.x;
            KVs[(c4 + 1) * FL_BN + r] = t.y;
            KVs[(c4 + 2) * FL_BN + r] = t.z;
            KVs[(c4 + 3) * FL_BN + r] = t.w;
        }
        __syncthreads();

        float acc[4][4];
        #pragma unroll
        for (int r = 0; r < 4; r++)
            #pragma unroll
            for (int c = 0; c < 4; c++) acc[r][c] = 0.f;

        #pragma unroll 4
        for (int d = 0; d < HD_; d++) {
            float4 qa = *(float4*)&Qs[d * FL_BM + ty * 4];
            float4 kb = *(float4*)&KVs[d * FL_BN + tx * 4];
            float qr[4] = {qa.x, qa.y, qa.z, qa.w};
            float kr[4] = {kb.x, kb.y, kb.z, kb.w};
            #pragma unroll
            for (int r = 0; r < 4; r++)
                #pragma unroll
                for (int c = 0; c < 4; c++)
                    acc[r][c] = fmaf(qr[r], kr[c], acc[r][c]);
        }
        __syncthreads();

        for (int it = tid; it < FL_BN * (HD_ / 4); it += 256) {
            const int r  = it >> 5;
            const int c4 = (it & 31) << 2;
            *(float4*)&KVs[r * HD_ + c4] =
                *(const float4*)&Vg[(size_t)(k0 + r) * HD_ + c4];
        }

        if (j == jmax) {
            #pragma unroll
            for (int r = 0; r < 4; r++)
                #pragma unroll
                for (int c = 0; c < 4; c++)
                    if (k0 + tx * 4 + c > q0 + ty * 4 + r) acc[r][c] = -1e30f;
        }

        float p[4][4];
        #pragma unroll
        for (int r = 0; r < 4; r++) {
            float mt = fmaxf(fmaxf(acc[r][0], acc[r][1]),
                             fmaxf(acc[r][2], acc[r][3]));
            mt = rowmax16(mt);
            const float mn = fmaxf(m[r], mt);
            const float alpha = __expf(m[r] - mn);
            m[r] = mn;
            float ls = 0.f;
            #pragma unroll
            for (int c = 0; c < 4; c++) {
                p[r][c] = __expf(acc[r][c] - mn);
                ls += p[r][c];
            }
            ls = rowsum16(ls);
            l[r] = l[r] * alpha + ls;
            #pragma unroll
            for (int c = 0; c < 8; c++) O[r][c] *= alpha;
        }

        #pragma unroll
        for (int r = 0; r < 4; r++)
            #pragma unroll
            for (int c = 0; c < 4; c++)
                Ps[(ty * 4 + r) * (FL_BN + 1) + tx * 4 + c] = p[r][c];
        __syncthreads();

        #pragma unroll 2
        for (int kk = 0; kk < FL_BN; kk++) {
            float pr[4];
            #pragma unroll
            for (int r = 0; r < 4; r++)
                pr[r] = Ps[(ty * 4 + r) * (FL_BN + 1) + kk];
            float4 v0 = *(float4*)&KVs[kk * HD_ + tx * 8];
            float4 v1 = *(float4*)&KVs[kk * HD_ + tx * 8 + 4];
            float vr[8] = {v0.x, v0.y, v0.z, v0.w, v1.x, v1.y, v1.z, v1.w};
            #pragma unroll
            for (int r = 0; r < 4; r++)
                #pragma unroll
                for (int c = 0; c < 8; c++)
                    O[r][c] = fmaf(pr[r], vr[c], O[r][c]);
        }
    }

    #pragma unroll
    for (int r = 0; r < 4; r++) {
        const float inv = 1.f / l[r];
        const int row = q0 + ty * 4 + r;
        float* cp = &ctx[((size_t)(b * SQ_ + row)) * H_ + h * HD_ + tx * 8];
        float4 o0 = make_float4(O[r][0]*inv, O[r][1]*inv, O[r][2]*inv, O[r][3]*inv);
        float4 o1 = make_float4(O[r][4]*inv, O[r][5]*inv, O[r][6]*inv, O[r][7]*inv);
        *(float4*)&cp[0] = o0;
        *(float4*)&cp[4] = o1;
    }
}

// ---------------------------------------------------------------------------
// Launch
// ---------------------------------------------------------------------------
extern "C" void kernel_launch(void* const* d_in, const int* in_sizes, int n_in,
                              void* d_out, int out_size)
{
    const float* hidden = (const float*)d_in[0];
    const float* rope   = (const float*)d_in[1];
    const float* Wqkv   = (const float*)d_in[2];   // [4096, 4608]
    const float* bqkv   = (const float*)d_in[3];
    const float* Wd     = (const float*)d_in[4];   // [4096, 4096]
    float* out = (float*)d_out;

    float *mixed, *qp, *kp, *vp, *ctx;
    __nv_bfloat16 *as, *bs;
    cudaGetSymbolAddress((void**)&mixed, g_mixed);
    cudaGetSymbolAddress((void**)&qp,    g_q);
    cudaGetSymbolAddress((void**)&kp,    g_k);
    cudaGetSymbolAddress((void**)&vp,    g_v);
    cudaGetSymbolAddress((void**)&ctx,   g_ctx);
    cudaGetSymbolAddress((void**)&as,    g_as);
    cudaGetSymbolAddress((void**)&bs,    g_bs);

    cudaFuncSetAttribute(mma_gemm_kernel,
                         cudaFuncAttributeMaxDynamicSharedMemorySize, GEMM_SMEM_BYTES);
    cudaFuncSetAttribute(flash_kernel,
                         cudaFuncAttributeMaxDynamicSharedMemorySize, FLASH_SMEM_BYTES);

    const size_t n8 = (size_t)MM_ * H_ / 8;

    // 1) split hidden -> As [M, 3K]; transpose+split Wqkv -> Bs [4608, 3K]
    split_a_kernel<<<(unsigned)((n8 + 255) / 256), 256>>>(hidden, as, H_, n8);
    transpose_split_kernel<<<dim3(QKV_OUT_ / 32, H_ / 32), 256>>>(Wqkv, bs, H_, QKV_OUT_);

    // 2) mixed = hidden @ Wqkv + bias (tensor cores, split-K' bf16)
    mma_gemm_kernel<<<dim3(QKV_OUT_ / GBN, MM_ / GBM), 256, GEMM_SMEM_BYTES>>>(
        as, bs, bqkv, mixed, QKV_OUT_, KSPLIT_);

    // 3) RoPE + scatter
    rope_scatter_kernel<<<dim3(NH_ + 2 * NG_, SQ_, B_), 128>>>(mixed, rope, qp, kp, vp);

    // 4) causal GQA flash attention (fp32)
    flash_kernel<<<dim3(SQ_ / FL_BM, NH_, B_), 256, FLASH_SMEM_BYTES>>>(qp, kp, vp, ctx);

    // 5) split ctx -> As; transpose+split Wd -> Bs [4096, 3K]
    split_a_kernel<<<(unsigned)((n8 + 255) / 256), 256>>>(ctx, as, H_, n8);
    transpose_split_kernel<<<dim3(H_ / 32, H_ / 32), 256>>>(Wd, bs, H_, H_);

    // 6) out = ctx @ Wd (tensor cores)
    mma_gemm_kernel<<<dim3(H_ / GBN, MM_ / GBM), 256, GEMM_SMEM_BYTES>>>(
        as, bs, nullptr, out, H_, KSPLIT_);
}

// round 4
// speedup vs baseline: 2.5854x; 1.7600x over previous
#include <cuda_runtime.h>
#include <cuda_bf16.h>
#include <cstdint>
#include <math.h>

// ---------------------------------------------------------------------------
// Problem constants
// ---------------------------------------------------------------------------
#define B_     2
#define SQ_    2048
#define H_     4096
#define NH_    32
#define HD_    128
#define NG_    2
#define QKV_OUT_ (NH_*HD_ + 2*NG_*HD_)   // 4608
#define Q_SZ_    (NH_*HD_)               // 4096
#define KV_SZ_   (NG_*HD_)               // 256
#define REP_     (NH_/NG_)               // 16
#define MM_      (B_*SQ_)                // 4096
#define KSPLIT_  (3*H_)                  // 12288

// ---------------------------------------------------------------------------
// Scratch
// ---------------------------------------------------------------------------
__device__ float g_mixed[(size_t)MM_*QKV_OUT_];
__device__ __nv_bfloat16 g_as[(size_t)MM_*KSPLIT_];
__device__ __nv_bfloat16 g_bs[(size_t)QKV_OUT_*KSPLIT_];
// bf16 hi/lo Q (pre-scaled), K, V
__device__ __nv_bfloat16 g_qh[(size_t)B_*NH_*SQ_*HD_];
__device__ __nv_bfloat16 g_ql[(size_t)B_*NH_*SQ_*HD_];
__device__ __nv_bfloat16 g_kh[(size_t)B_*NG_*SQ_*HD_];
__device__ __nv_bfloat16 g_kl[(size_t)B_*NG_*SQ_*HD_];
__device__ __nv_bfloat16 g_vh[(size_t)B_*NG_*SQ_*HD_];
__device__ __nv_bfloat16 g_vl[(size_t)B_*NG_*SQ_*HD_];

// ---------------------------------------------------------------------------
// Helpers
// ---------------------------------------------------------------------------
__device__ __forceinline__ uint32_t smem_u32(const void* p) {
    uint32_t a;
    asm("{ .reg .u64 t; cvta.to.shared.u64 t, %1; cvt.u32.u64 %0, t; }" : "=r"(a) : "l"(p));
    return a;
}
__device__ __forceinline__ void cp_async16(uint32_t dst, const void* src) {
    asm volatile("cp.async.cg.shared.global [%0], [%1], 16;" :: "r"(dst), "l"(src));
}
__device__ __forceinline__ void cp_commit() {
    asm volatile("cp.async.commit_group;");
}
template<int N>
__device__ __forceinline__ void cp_wait() {
    asm volatile("cp.async.wait_group %0;" :: "n"(N));
}
__device__ __forceinline__ void ldm_x4(uint32_t& r0, uint32_t& r1, uint32_t& r2,
                                       uint32_t& r3, uint32_t addr) {
    asm volatile("ldmatrix.sync.aligned.m8n8.x4.shared.b16 {%0,%1,%2,%3}, [%4];"
                 : "=r"(r0), "=r"(r1), "=r"(r2), "=r"(r3) : "r"(addr));
}
__device__ __forceinline__ void ldm_x4_t(uint32_t& r0, uint32_t& r1, uint32_t& r2,
                                         uint32_t& r3, uint32_t addr) {
    asm volatile("ldmatrix.sync.aligned.m8n8.x4.trans.shared.b16 {%0,%1,%2,%3}, [%4];"
                 : "=r"(r0), "=r"(r1), "=r"(r2), "=r"(r3) : "r"(addr));
}
__device__ __forceinline__ void mma_bf16(float* d, const uint32_t* a,
                                         uint32_t b0, uint32_t b1) {
    asm volatile(
        "mma.sync.aligned.m16n8k16.row.col.f32.bf16.bf16.f32 "
        "{%0,%1,%2,%3}, {%4,%5,%6,%7}, {%8,%9}, {%0,%1,%2,%3};"
        : "+f"(d[0]), "+f"(d[1]), "+f"(d[2]), "+f"(d[3])
        : "r"(a[0]), "r"(a[1]), "r"(a[2]), "r"(a[3]), "r"(b0), "r"(b1));
}
__device__ __forceinline__ void split_pack(uint32_t& hi, uint32_t& lo, float p0, float p1) {
    __nv_bfloat16 h0 = __float2bfloat16(p0), h1 = __float2bfloat16(p1);
    __nv_bfloat16 e0 = __float2bfloat16(p0 - __bfloat162float(h0));
    __nv_bfloat16 e1 = __float2bfloat16(p1 - __bfloat162float(h1));
    hi = (uint32_t)__bfloat16_as_ushort(h0) | ((uint32_t)__bfloat16_as_ushort(h1) << 16);
    lo = (uint32_t)__bfloat16_as_ushort(e0) | ((uint32_t)__bfloat16_as_ushort(e1) << 16);
}

// ---------------------------------------------------------------------------
// fp32 -> bf16 hi/lo split kernels
// ---------------------------------------------------------------------------
// A[M,K] fp32 -> As[M, 3K] bf16, segments [hi | lo | hi]
__global__ __launch_bounds__(256)
void split_a_kernel(const float* __restrict__ A, __nv_bfloat16* __restrict__ As,
                    int K, size_t n8)
{
    size_t g = (size_t)blockIdx.x * 256 + threadIdx.x;
    if (g >= n8) return;
    const int kpr = K / 8;
    const size_t m  = g / kpr;
    const int   k8  = (int)(g % kpr) * 8;
    float4 a0 = *(const float4*)&A[m * K + k8];
    float4 a1 = *(const float4*)&A[m * K + k8 + 4];
    float v[8] = {a0.x,a0.y,a0.z,a0.w,a1.x,a1.y,a1.z,a1.w};
    __nv_bfloat162 h[4], l[4];
    #pragma unroll
    for (int j = 0; j < 4; j++) {
        __nv_bfloat16 h0 = __float2bfloat16(v[2*j]);
        __nv_bfloat16 h1 = __float2bfloat16(v[2*j+1]);
        h[j] = __nv_bfloat162(h0, h1);
        l[j] = __nv_bfloat162(__float2bfloat16(v[2*j]   - __bfloat162float(h0)),
                              __float2bfloat16(v[2*j+1] - __bfloat162float(h1)));
    }
    __nv_bfloat16* row = As + m * (size_t)(3*K);
    *(uint4*)&row[k8]       = *(uint4*)h;
    *(uint4*)&row[K + k8]   = *(uint4*)l;
    *(uint4*)&row[2*K + k8] = *(uint4*)h;
}

// W[K,N] fp32 -> Bs[N, 3K] bf16 (transposed), segments [hi | hi | lo]
__global__ __launch_bounds__(256)
void transpose_split_kernel(const float* __restrict__ W, __nv_bfloat16* __restrict__ Bs,
                            int K, int N)
{
    __shared__ float t[32][33];
    const int n0 = blockIdx.x * 32, k0 = blockIdx.y * 32;
    const int tx = threadIdx.x & 31, ty = threadIdx.x >> 5;
    #pragma unroll
    for (int i = 0; i < 4; i++)
        t[ty + 8*i][tx] = W[(size_t)(k0 + ty + 8*i) * N + n0 + tx];
    __syncthreads();
    #pragma unroll
    for (int i = 0; i < 4; i++) {
        float v = t[tx][ty + 8*i];
        __nv_bfloat16 h = __float2bfloat16(v);
        __nv_bfloat16 l = __float2bfloat16(v - __bfloat162float(h));
        __nv_bfloat16* row = Bs + (size_t)(n0 + ty + 8*i) * (3*K);
        row[k0 + tx]       = h;
        row[K + k0 + tx]   = h;
        row[2*K + k0 + tx] = l;
    }
}

// ---------------------------------------------------------------------------
// bf16 tensor-core GEMM (unchanged from R3)
// ---------------------------------------------------------------------------
#define GBM 128
#define GBN 128
#define GBK 32
#define GLD 40
#define STG_A_BYTES (GBM*GLD*2)
#define STG_BYTES   ((GBM+GBN)*GLD*2)
#define GSTAGES 3
#define GEMM_SMEM_BYTES (GSTAGES*STG_BYTES)

__global__ __launch_bounds__(256)
void mma_gemm_kernel(const __nv_bfloat16* __restrict__ Ag,
                     const __nv_bfloat16* __restrict__ Bg,
                     const float* __restrict__ bias, float* __restrict__ C,
                     int N, int Kp)
{
    extern __shared__ char dsm[];
    const uint32_t sbase = smem_u32(dsm);

    const int tid  = threadIdx.x;
    const int lane = tid & 31;
    const int wid  = tid >> 5;
    const int wm   = wid >> 2;
    const int wn   = wid & 3;
    const int m0   = blockIdx.y * GBM;
    const int n0   = blockIdx.x * GBN;

    const __nv_bfloat16* Arow = Ag + (size_t)m0 * Kp;
    const __nv_bfloat16* Brow = Bg + (size_t)n0 * Kp;

    const int NIT = Kp / GBK;

    auto issue_stage = [&](int kt, int slot) {
        const uint32_t sa = sbase + slot * STG_BYTES;
        const uint32_t sb = sa + STG_A_BYTES;
        const int kO = kt * GBK;
        #pragma unroll
        for (int h = 0; h < 2; h++) {
            const int g = tid + h * 256;
            const int r = g >> 2, c = g & 3;
            cp_async16(sa + (r * GLD + c * 8) * 2,
                       Arow + (size_t)r * Kp + kO + c * 8);
            cp_async16(sb + (r * GLD + c * 8) * 2,
                       Brow + (size_t)r * Kp + kO + c * 8);
        }
        cp_commit();
    };

    float acc[4][4][4];
    #pragma unroll
    for (int i = 0; i < 4; i++)
        #pragma unroll
        for (int j = 0; j < 4; j++)
            #pragma unroll
            for (int r = 0; r < 4; r++) acc[i][j][r] = 0.f;

    issue_stage(0, 0);
    issue_stage(1, 1);

    const int a_r = lane & 15;
    const int a_c = (lane >> 4) << 3;
    const int b_r = (lane & 7) + ((lane >> 4) << 3);
    const int b_c = ((lane >> 3) & 1) << 3;

    for (int kt = 0; kt < NIT; kt++) {
        cp_wait<1>();
        __syncthreads();
        if (kt + 2 < NIT) issue_stage(kt + 2, (kt + 2) % GSTAGES);
        else cp_commit();

        const int slot = kt % GSTAGES;
        const uint32_t sa = sbase + slot * STG_BYTES;
        const uint32_t sb = sa + STG_A_BYTES;

        #pragma unroll
        for (int ks = 0; ks < 2; ks++) {
            const int kb = ks * 16;
            uint32_t a[4][4];
            #pragma unroll
            for (int i = 0; i < 4; i++)
                ldm_x4(a[i][0], a[i][1], a[i][2], a[i][3],
                       sa + ((wm*64 + i*16 + a_r) * GLD + kb + a_c) * 2);
            uint32_t b[4][2];
            #pragma unroll
            for (int j = 0; j < 2; j++) {
                uint32_t r0, r1, r2, r3;
                ldm_x4(r0, r1, r2, r3,
                       sb + ((wn*32 + j*16 + b_r) * GLD + kb + b_c) * 2);
                b[j*2][0]   = r0; b[j*2][1]   = r1;
                b[j*2+1][0] = r2; b[j*2+1][1] = r3;
            }
            #pragma unroll
            for (int i = 0; i < 4; i++)
                #pragma unroll
                for (int j = 0; j < 4; j++)
                    mma_bf16(acc[i][j], a[i], b[j][0], b[j][1]);
        }
        __syncthreads();
    }

    const int cr = lane >> 2;
    const int cc = (lane & 3) * 2;
    #pragma unroll
    for (int j = 0; j < 4; j++) {
        const int col = n0 + wn*32 + j*8 + cc;
        float2 bv = make_float2(0.f, 0.f);
        if (bias) bv = *(const float2*)&bias[col];
        #pragma unroll
        for (int i = 0; i < 4; i++) {
            const int row = m0 + wm*64 + i*16 + cr;
            *(float2*)&C[(size_t)row * N + col] =
                make_float2(acc[i][j][0] + bv.x, acc[i][j][1] + bv.y);
            *(float2*)&C[(size_t)(row + 8) * N + col] =
                make_float2(acc[i][j][2] + bv.x, acc[i][j][3] + bv.y);
        }
    }
}

// ---------------------------------------------------------------------------
// RoPE + scatter -> bf16 hi/lo Q (scaled), K, V
// ---------------------------------------------------------------------------
__global__ __launch_bounds__(128)
void rope_scatter_kernel(const float* __restrict__ mixed,
                         const float* __restrict__ cache,
                         __nv_bfloat16* __restrict__ qh, __nv_bfloat16* __restrict__ ql,
                         __nv_bfloat16* __restrict__ kh, __nv_bfloat16* __restrict__ kl,
                         __nv_bfloat16* __restrict__ vh, __nv_bfloat16* __restrict__ vl)
{
    const int head = blockIdx.x;
    const int s    = blockIdx.y;
    const int b    = blockIdx.z;
    const int j    = threadIdx.x;

    const float* row = mixed + ((size_t)(b * SQ_ + s)) * QKV_OUT_;
    const float scale = 0.08838834764831845f;   // 1/sqrt(128)

    float out;
    size_t off;
    __nv_bfloat16 *dh, *dl;
    if (head < NH_ + NG_) {
        const float* x = (head < NH_) ? (row + head * HD_)
                                      : (row + Q_SZ_ + (head - NH_) * HD_);
        if (j < 64) {
            const int p = j >> 1;
            const float x0 = x[2 * p], x1 = x[2 * p + 1];
            const float c0 = cache[((size_t)s * 32 + p) * 2 + 0];
            const float c1 = cache[((size_t)s * 32 + p) * 2 + 1];
            out = (j & 1) ? fmaf(x1, c0, x0 * c1) : fmaf(x0, c0, -x1 * c1);
        } else {
            out = x[j];
        }
        if (head < NH_) {
            out *= scale;
            off = (((size_t)b * NH_ + head) * SQ_ + s) * HD_ + j;
            dh = qh; dl = ql;
        } else {
            off = (((size_t)b * NG_ + (head - NH_)) * SQ_ + s) * HD_ + j;
            dh = kh; dl = kl;
        }
    } else {
        const int g = head - NH_ - NG_;
        out = row[Q_SZ_ + KV_SZ_ + g * HD_ + j];
        off = (((size_t)b * NG_ + g) * SQ_ + s) * HD_ + j;
        dh = vh; dl = vl;
    }
    __nv_bfloat16 h = __float2bfloat16(out);
    dh[off] = h;
    dl[off] = __float2bfloat16(out - __bfloat162float(h));
}

// ---------------------------------------------------------------------------
// Tensor-core flash attention (bf16 hi/lo split, fp32 softmax/accum)
// CTA: 128 q-rows (8 warps x m16), kv tiles of 64, K/V double-buffered.
// Output written directly into split-As layout [hi | lo | hi] over 3K.
// ---------------------------------------------------------------------------
#define FBM 128
#define FBN 64
#define KV_TILE_B (FBN*256)          // 16 KB per tile
#define FB_BUF    (4*KV_TILE_B)      // Kh,Kl,Vh,Vl
#define FLASH2_SMEM (2*FB_BUF)       // 128 KB

#define SWZ(row, gr) ((uint32_t)((row)*256 + ((((uint32_t)(gr)) ^ ((row)&7)) << 4)))

__global__ __launch_bounds__(256, 1)
void flash_mma_kernel(const __nv_bfloat16* __restrict__ Qh, const __nv_bfloat16* __restrict__ Ql,
                      const __nv_bfloat16* __restrict__ Kh, const __nv_bfloat16* __restrict__ Kl,
                      const __nv_bfloat16* __restrict__ Vh, const __nv_bfloat16* __restrict__ Vl,
                      __nv_bfloat16* __restrict__ As)
{
    extern __shared__ char dsm[];
    const uint32_t sb = smem_u32(dsm);

    const int qb = gridDim.x - 1 - blockIdx.x;     // longest first
    const int h  = blockIdx.y;
    const int b  = blockIdx.z;
    const int g  = h / REP_;

    const int tid  = threadIdx.x;
    const int lane = tid & 31;
    const int wid  = tid >> 5;
    const int q0   = qb * FBM;
    const int qrow = q0 + wid * 16;
    const int r1   = lane >> 2;          // 0..7
    const int c2   = (lane & 3) * 2;
    const int grp  = lane >> 3;
    const int ri   = lane & 7;

    const __nv_bfloat16* Qhp = Qh + ((size_t)b * NH_ + h) * SQ_ * HD_;
    const __nv_bfloat16* Qlp = Ql + ((size_t)b * NH_ + h) * SQ_ * HD_;
    const __nv_bfloat16* Khp = Kh + ((size_t)b * NG_ + g) * SQ_ * HD_;
    const __nv_bfloat16* Klp = Kl + ((size_t)b * NG_ + g) * SQ_ * HD_;
    const __nv_bfloat16* Vhp = Vh + ((size_t)b * NG_ + g) * SQ_ * HD_;
    const __nv_bfloat16* Vlp = Vl + ((size_t)b * NG_ + g) * SQ_ * HD_;

    // --- Q fragments to registers (once) ---
    uint32_t qfh[8][4], qfl[8][4];
    #pragma unroll
    for (int kc = 0; kc < 8; kc++) {
        const int col = kc * 16 + c2;
        qfh[kc][0] = *(const uint32_t*)&Qhp[(size_t)(qrow + r1)     * HD_ + col];
        qfh[kc][1] = *(const uint32_t*)&Qhp[(size_t)(qrow + r1 + 8) * HD_ + col];
        qfh[kc][2] = *(const uint32_t*)&Qhp[(size_t)(qrow + r1)     * HD_ + col + 8];
        qfh[kc][3] = *(const uint32_t*)&Qhp[(size_t)(qrow + r1 + 8) * HD_ + col + 8];
        qfl[kc][0] = *(const uint32_t*)&Qlp[(size_t)(qrow + r1)     * HD_ + col];
        qfl[kc][1] = *(const uint32_t*)&Qlp[(size_t)(qrow + r1 + 8) * HD_ + col];
        qfl[kc][2] = *(const uint32_t*)&Qlp[(size_t)(qrow + r1)     * HD_ + col + 8];
        qfl[kc][3] = *(const uint32_t*)&Qlp[(size_t)(qrow + r1 + 8) * HD_ + col + 8];
    }

    float o[16][4];
    #pragma unroll
    for (int j = 0; j < 16; j++)
        #pragma unroll
        for (int e = 0; e < 4; e++) o[j][e] = 0.f;
    float m1 = -1e30f, m2 = -1e30f, l1 = 0.f, l2 = 0.f;

    auto issue_kv = [&](int jt, int buf) {
        const uint32_t bbase = sb + (uint32_t)buf * FB_BUF;
        const int s0 = jt * FBN;
        const __nv_bfloat16* srcs[4] = {
            Khp + (size_t)s0 * HD_, Klp + (size_t)s0 * HD_,
            Vhp + (size_t)s0 * HD_, Vlp + (size_t)s0 * HD_ };
        #pragma unroll
        for (int t = 0; t < 4; t++) {
            #pragma unroll
            for (int i = 0; i < 4; i++) {
                const int gg = tid + i * 256;     // 0..1023
                const int row = gg >> 4, c = gg & 15;
                cp_async16(bbase + t * KV_TILE_B + SWZ(row, c),
                           srcs[t] + (size_t)row * HD_ + c * 8);
            }
        }
        cp_commit();
    };

    const int njt = 2 * qb + 2;
    issue_kv(0, 0);

    for (int jt = 0; jt < njt; jt++) {
        if (jt + 1 < njt) { issue_kv(jt + 1, (jt + 1) & 1); cp_wait<1>(); }
        else              { cp_wait<0>(); }
        __syncthreads();

        const uint32_t bbase = sb + (uint32_t)(jt & 1) * FB_BUF;
        const uint32_t khb = bbase;
        const uint32_t klb = bbase + KV_TILE_B;
        const uint32_t vhb = bbase + 2 * KV_TILE_B;
        const uint32_t vlb = bbase + 3 * KV_TILE_B;

        // ---- S = Q @ K^T ----
        float s[8][4];
        #pragma unroll
        for (int j = 0; j < 8; j++)
            #pragma unroll
            for (int e = 0; e < 4; e++) s[j][e] = 0.f;

        #pragma unroll
        for (int kc = 0; kc < 8; kc++) {
            #pragma unroll
            for (int np = 0; np < 4; np++) {
                const int krow = np * 16 + ri + ((grp >> 1) << 3);
                const int kgr  = 2 * kc + (grp & 1);
                uint32_t h0,h1,h2,h3,l0,l1r,l2r,l3;
                ldm_x4(h0, h1, h2, h3, khb + SWZ(krow, kgr));
                ldm_x4(l0, l1r, l2r, l3, klb + SWZ(krow, kgr));
                mma_bf16(s[2*np],   qfh[kc], h0, h1);
                mma_bf16(s[2*np+1], qfh[kc], h2, h3);
                mma_bf16(s[2*np],   qfl[kc], h0, h1);
                mma_bf16(s[2*np+1], qfl[kc], h2, h3);
                mma_bf16(s[2*np],   qfh[kc], l0, l1r);
                mma_bf16(s[2*np+1], qfh[kc], l2r, l3);
            }
        }

        // ---- causal mask (only last two tiles can clip) ----
        if (jt >= 2 * qb) {
            const int row1 = qrow + r1, row2 = row1 + 8;
            #pragma unroll
            for (int j = 0; j < 8; j++) {
                const int col = jt * FBN + j * 8 + c2;
                if (col     > row1) s[j][0] = -1e30f;
                if (col + 1 > row1) s[j][1] = -1e30f;
                if (col     > row2) s[j][2] = -1e30f;
                if (col + 1 > row2) s[j][3] = -1e30f;
            }
        }

        // ---- online softmax ----
        float mx1 = -1e30f, mx2 = -1e30f;
        #pragma unroll
        for (int j = 0; j < 8; j++) {
            mx1 = fmaxf(mx1, fmaxf(s[j][0], s[j][1]));
            mx2 = fmaxf(mx2, fmaxf(s[j][2], s[j][3]));
        }
        mx1 = fmaxf(mx1, __shfl_xor_sync(0xffffffffu, mx1, 1));
        mx1 = fmaxf(mx1, __shfl_xor_sync(0xffffffffu, mx1, 2));
        mx2 = fmaxf(mx2, __shfl_xor_sync(0xffffffffu, mx2, 1));
        mx2 = fmaxf(mx2, __shfl_xor_sync(0xffffffffu, mx2, 2));

        const float mn1 = fmaxf(m1, mx1), mn2 = fmaxf(m2, mx2);
        const float a1 = __expf(m1 - mn1), a2 = __expf(m2 - mn2);
        m1 = mn1; m2 = mn2;

        float sum1 = 0.f, sum2 = 0.f;
        #pragma unroll
        for (int j = 0; j < 8; j++) {
            s[j][0] = __expf(s[j][0] - mn1);
            s[j][1] = __expf(s[j][1] - mn1);
            s[j][2] = __expf(s[j][2] - mn2);
            s[j][3] = __expf(s[j][3] - mn2);
            sum1 += s[j][0] + s[j][1];
            sum2 += s[j][2] + s[j][3];
        }
        sum1 += __shfl_xor_sync(0xffffffffu, sum1, 1);
        sum1 += __shfl_xor_sync(0xffffffffu, sum1, 2);
        sum2 += __shfl_xor_sync(0xffffffffu, sum2, 1);
        sum2 += __shfl_xor_sync(0xffffffffu, sum2, 2);
        l1 = l1 * a1 + sum1;
        l2 = l2 * a2 + sum2;

        #pragma unroll
        for (int j = 0; j < 16; j++) {
            o[j][0] *= a1; o[j][1] *= a1;
            o[j][2] *= a2; o[j][3] *= a2;
        }

        // ---- O += P @ V ----
        #pragma unroll
        for (int t = 0; t < 4; t++) {
            uint32_t ph[4], pl[4];
            split_pack(ph[0], pl[0], s[2*t][0],   s[2*t][1]);
            split_pack(ph[1], pl[1], s[2*t][2],   s[2*t][3]);
            split_pack(ph[2], pl[2], s[2*t+1][0], s[2*t+1][1]);
            split_pack(ph[3], pl[3], s[2*t+1][2], s[2*t+1][3]);
            #pragma unroll
            for (int np = 0; np < 8; np++) {
                const int vrow = t * 16 + ri + ((grp & 1) << 3);
                const int vgr  = 2 * np + (grp >> 1);
                uint32_t h0,h1,h2,h3,l0,l1r,l2r,l3;
                ldm_x4_t(h0, h1, h2, h3, vhb + SWZ(vrow, vgr));
                ldm_x4_t(l0, l1r, l2r, l3, vlb + SWZ(vrow, vgr));
                mma_bf16(o[2*np],   ph, h0, h1);
                mma_bf16(o[2*np+1], ph, h2, h3);
                mma_bf16(o[2*np],   pl, h0, h1);
                mma_bf16(o[2*np+1], pl, h2, h3);
                mma_bf16(o[2*np],   ph, l0, l1r);
                mma_bf16(o[2*np+1], ph, l2r, l3);
            }
        }
        __syncthreads();
    }

    // ---- epilogue: write split-As layout [hi | lo | hi] ----
    const float inv1 = 1.f / l1, inv2 = 1.f / l2;
    const size_t mr1 = (size_t)b * SQ_ + qrow + r1;
    const size_t mr2 = mr1 + 8;
    #pragma unroll
    for (int j = 0; j < 16; j++) {
        const int col = h * HD_ + j * 8 + c2;
        uint32_t hi, lo;
        split_pack(hi, lo, o[j][0] * inv1, o[j][1] * inv1);
        *(uint32_t*)&As[mr1 * KSPLIT_ + col]          = hi;
        *(uint32_t*)&As[mr1 * KSPLIT_ + H_ + col]     = lo;
        *(uint32_t*)&As[mr1 * KSPLIT_ + 2*H_ + col]   = hi;
        split_pack(hi, lo, o[j][2] * inv2, o[j][3] * inv2);
        *(uint32_t*)&As[mr2 * KSPLIT_ + col]          = hi;
        *(uint32_t*)&As[mr2 * KSPLIT_ + H_ + col]     = lo;
        *(uint32_t*)&As[mr2 * KSPLIT_ + 2*H_ + col]   = hi;
    }
}

// ---------------------------------------------------------------------------
// Launch
// ---------------------------------------------------------------------------
extern "C" void kernel_launch(void* const* d_in, const int* in_sizes, int n_in,
                              void* d_out, int out_size)
{
    const float* hidden = (const float*)d_in[0];
    const float* rope   = (const float*)d_in[1];
    const float* Wqkv   = (const float*)d_in[2];
    const float* bqkv   = (const float*)d_in[3];
    const float* Wd     = (const float*)d_in[4];
    float* out = (float*)d_out;

    float* mixed;
    __nv_bfloat16 *as, *bs, *qh, *ql, *kh, *kl, *vh, *vl;
    cudaGetSymbolAddress((void**)&mixed, g_mixed);
    cudaGetSymbolAddress((void**)&as, g_as);
    cudaGetSymbolAddress((void**)&bs, g_bs);
    cudaGetSymbolAddress((void**)&qh, g_qh);
    cudaGetSymbolAddress((void**)&ql, g_ql);
    cudaGetSymbolAddress((void**)&kh, g_kh);
    cudaGetSymbolAddress((void**)&kl, g_kl);
    cudaGetSymbolAddress((void**)&vh, g_vh);
    cudaGetSymbolAddress((void**)&vl, g_vl);

    cudaFuncSetAttribute(mma_gemm_kernel,
                         cudaFuncAttributeMaxDynamicSharedMemorySize, GEMM_SMEM_BYTES);
    cudaFuncSetAttribute(flash_mma_kernel,
                         cudaFuncAttributeMaxDynamicSharedMemorySize, FLASH2_SMEM);

    const size_t n8 = (size_t)MM_ * H_ / 8;

    // 1) split hidden -> As; transpose+split Wqkv -> Bs
    split_a_kernel<<<(unsigned)((n8 + 255) / 256), 256>>>(hidden, as, H_, n8);
    transpose_split_kernel<<<dim3(QKV_OUT_ / 32, H_ / 32), 256>>>(Wqkv, bs, H_, QKV_OUT_);

    // 2) mixed = hidden @ Wqkv + bias
    mma_gemm_kernel<<<dim3(QKV_OUT_ / GBN, MM_ / GBM), 256, GEMM_SMEM_BYTES>>>(
        as, bs, bqkv, mixed, QKV_OUT_, KSPLIT_);

    // 3) RoPE + scatter -> bf16 hi/lo q/k/v
    rope_scatter_kernel<<<dim3(NH_ + 2 * NG_, SQ_, B_), 128>>>(
        mixed, rope, qh, ql, kh, kl, vh, vl);

    // 4) tensor-core flash attention -> writes split-As directly
    flash_mma_kernel<<<dim3(SQ_ / FBM, NH_, B_), 256, FLASH2_SMEM>>>(
        qh, ql, kh, kl, vh, vl, as);

    // 5) transpose+split Wd -> Bs
    transpose_split_kernel<<<dim3(H_ / 32, H_ / 32), 256>>>(Wd, bs, H_, H_);

    // 6) out = ctx @ Wd
    mma_gemm_kernel<<<dim3(H_ / GBN, MM_ / GBM), 256, GEMM_SMEM_BYTES>>>(
        as, bs, nullptr, out, H_, KSPLIT_);
}

// round 5
// speedup vs baseline: 2.7332x; 1.0572x over previous
#include <cuda_runtime.h>
#include <cuda_fp16.h>
#include <cstdint>
#include <math.h>

// ---------------------------------------------------------------------------
// Problem constants
// ---------------------------------------------------------------------------
#define B_     2
#define SQ_    2048
#define H_     4096
#define NH_    32
#define HD_    128
#define NG_    2
#define QKV_OUT_ (NH_*HD_ + 2*NG_*HD_)   // 4608
#define Q_SZ_    (NH_*HD_)               // 4096
#define KV_SZ_   (NG_*HD_)               // 256
#define REP_     (NH_/NG_)               // 16
#define MM_      (B_*SQ_)                // 4096
#define KSPLIT_  (3*H_)                  // 12288

#define SEG_UP   1024.0f                 // 2^10 lo-segment scale
#define SEG_DN   0.0009765625f           // 2^-10

// ---------------------------------------------------------------------------
// Scratch
// ---------------------------------------------------------------------------
__device__ float g_mixed[(size_t)MM_*QKV_OUT_];
__device__ __half g_as[(size_t)MM_*KSPLIT_];
__device__ __half g_bs[(size_t)QKV_OUT_*KSPLIT_];
// fp16 hi/lo Q (unscaled), K, V
__device__ __half g_qh[(size_t)B_*NH_*SQ_*HD_];
__device__ __half g_ql[(size_t)B_*NH_*SQ_*HD_];
__device__ __half g_kh[(size_t)B_*NG_*SQ_*HD_];
__device__ __half g_kl[(size_t)B_*NG_*SQ_*HD_];
__device__ __half g_vh[(size_t)B_*NG_*SQ_*HD_];
__device__ __half g_vl[(size_t)B_*NG_*SQ_*HD_];

// ---------------------------------------------------------------------------
// Helpers
// ---------------------------------------------------------------------------
__device__ __forceinline__ uint32_t smem_u32(const void* p) {
    uint32_t a;
    asm("{ .reg .u64 t; cvta.to.shared.u64 t, %1; cvt.u32.u64 %0, t; }" : "=r"(a) : "l"(p));
    return a;
}
__device__ __forceinline__ void cp_async16(uint32_t dst, const void* src) {
    asm volatile("cp.async.cg.shared.global [%0], [%1], 16;" :: "r"(dst), "l"(src));
}
__device__ __forceinline__ void cp_commit() {
    asm volatile("cp.async.commit_group;");
}
template<int N>
__device__ __forceinline__ void cp_wait() {
    asm volatile("cp.async.wait_group %0;" :: "n"(N));
}
__device__ __forceinline__ void ldm_x4(uint32_t& r0, uint32_t& r1, uint32_t& r2,
                                       uint32_t& r3, uint32_t addr) {
    asm volatile("ldmatrix.sync.aligned.m8n8.x4.shared.b16 {%0,%1,%2,%3}, [%4];"
                 : "=r"(r0), "=r"(r1), "=r"(r2), "=r"(r3) : "r"(addr));
}
__device__ __forceinline__ void ldm_x4_t(uint32_t& r0, uint32_t& r1, uint32_t& r2,
                                         uint32_t& r3, uint32_t addr) {
    asm volatile("ldmatrix.sync.aligned.m8n8.x4.trans.shared.b16 {%0,%1,%2,%3}, [%4];"
                 : "=r"(r0), "=r"(r1), "=r"(r2), "=r"(r3) : "r"(addr));
}
__device__ __forceinline__ void mma_f16(float* d, const uint32_t* a,
                                        uint32_t b0, uint32_t b1) {
    asm volatile(
        "mma.sync.aligned.m16n8k16.row.col.f32.f16.f16.f32 "
        "{%0,%1,%2,%3}, {%4,%5,%6,%7}, {%8,%9}, {%0,%1,%2,%3};"
        : "+f"(d[0]), "+f"(d[1]), "+f"(d[2]), "+f"(d[3])
        : "r"(a[0]), "r"(a[1]), "r"(a[2]), "r"(a[3]), "r"(b0), "r"(b1));
}
__device__ __forceinline__ uint32_t pack_h2(__half a, __half b) {
    return (uint32_t)__half_as_ushort(a) | ((uint32_t)__half_as_ushort(b) << 16);
}
__device__ __forceinline__ void split_pack(uint32_t& hi, uint32_t& lo, float p0, float p1) {
    __half h0 = __float2half(p0), h1 = __float2half(p1);
    __half e0 = __float2half(p0 - __half2float(h0));
    __half e1 = __float2half(p1 - __half2float(h1));
    hi = pack_h2(h0, h1);
    lo = pack_h2(e0, e1);
}

// ---------------------------------------------------------------------------
// fp32 -> fp16 hi/lo split kernels (scaled lo segments)
// ---------------------------------------------------------------------------
// A[M,K] fp32 -> As[M, 3K] fp16, segments [hi | lo*2^10 | hi*2^-10]
__global__ __launch_bounds__(256)
void split_a_kernel(const float* __restrict__ A, __half* __restrict__ As,
                    int K, size_t n8)
{
    size_t g = (size_t)blockIdx.x * 256 + threadIdx.x;
    if (g >= n8) return;
    const int kpr = K / 8;
    const size_t m  = g / kpr;
    const int   k8  = (int)(g % kpr) * 8;
    float4 a0 = *(const float4*)&A[m * K + k8];
    float4 a1 = *(const float4*)&A[m * K + k8 + 4];
    float v[8] = {a0.x,a0.y,a0.z,a0.w,a1.x,a1.y,a1.z,a1.w};
    uint32_t hseg[4], lseg[4], sseg[4];
    #pragma unroll
    for (int j = 0; j < 4; j++) {
        __half h0 = __float2half(v[2*j]);
        __half h1 = __float2half(v[2*j+1]);
        float f0 = __half2float(h0), f1 = __half2float(h1);
        hseg[j] = pack_h2(h0, h1);
        lseg[j] = pack_h2(__float2half((v[2*j]   - f0) * SEG_UP),
                          __float2half((v[2*j+1] - f1) * SEG_UP));
        sseg[j] = pack_h2(__float2half(f0 * SEG_DN), __float2half(f1 * SEG_DN));
    }
    __half* row = As + m * (size_t)(3*K);
    *(uint4*)&row[k8]       = *(uint4*)hseg;
    *(uint4*)&row[K + k8]   = *(uint4*)lseg;
    *(uint4*)&row[2*K + k8] = *(uint4*)sseg;
}

// W[K,N] fp32 -> Bs[N, 3K] fp16 (transposed), segments [hi | hi*2^-10 | lo*2^10]
__global__ __launch_bounds__(256)
void transpose_split_kernel(const float* __restrict__ W, __half* __restrict__ Bs,
                            int K, int N)
{
    __shared__ float t[32][33];
    const int n0 = blockIdx.x * 32, k0 = blockIdx.y * 32;
    const int tx = threadIdx.x & 31, ty = threadIdx.x >> 5;
    #pragma unroll
    for (int i = 0; i < 4; i++)
        t[ty + 8*i][tx] = W[(size_t)(k0 + ty + 8*i) * N + n0 + tx];
    __syncthreads();
    #pragma unroll
    for (int i = 0; i < 4; i++) {
        float v = t[tx][ty + 8*i];
        __half h = __float2half(v);
        float fh = __half2float(h);
        __half* row = Bs + (size_t)(n0 + ty + 8*i) * (3*K);
        row[k0 + tx]       = h;
        row[K + k0 + tx]   = __float2half(fh * SEG_DN);
        row[2*K + k0 + tx] = __float2half((v - fh) * SEG_UP);
    }
}

// ---------------------------------------------------------------------------
// fp16 tensor-core GEMM: C[M,N] = As[M,K'] @ Bs[N,K']^T
// BM=BN=128, BK=32, 8 warps, 4-stage cp.async pipeline.
// ---------------------------------------------------------------------------
#define GBM 128
#define GBN 128
#define GBK 32
#define GLD 40
#define STG_A_BYTES (GBM*GLD*2)
#define STG_BYTES   ((GBM+GBN)*GLD*2)
#define GSTAGES 4
#define GEMM_SMEM_BYTES (GSTAGES*STG_BYTES)   // 81920

__global__ __launch_bounds__(256)
void mma_gemm_kernel(const __half* __restrict__ Ag,
                     const __half* __restrict__ Bg,
                     const float* __restrict__ bias, float* __restrict__ C,
                     int N, int Kp)
{
    extern __shared__ char dsm[];
    const uint32_t sbase = smem_u32(dsm);

    const int tid  = threadIdx.x;
    const int lane = tid & 31;
    const int wid  = tid >> 5;
    const int wm   = wid >> 2;
    const int wn   = wid & 3;
    const int m0   = blockIdx.y * GBM;
    const int n0   = blockIdx.x * GBN;

    const __half* Arow = Ag + (size_t)m0 * Kp;
    const __half* Brow = Bg + (size_t)n0 * Kp;

    const int NIT = Kp / GBK;

    auto issue_stage = [&](int kt, int slot) {
        const uint32_t sa = sbase + slot * STG_BYTES;
        const uint32_t sb = sa + STG_A_BYTES;
        const int kO = kt * GBK;
        #pragma unroll
        for (int h = 0; h < 2; h++) {
            const int g = tid + h * 256;
            const int r = g >> 2, c = g & 3;
            cp_async16(sa + (r * GLD + c * 8) * 2,
                       Arow + (size_t)r * Kp + kO + c * 8);
            cp_async16(sb + (r * GLD + c * 8) * 2,
                       Brow + (size_t)r * Kp + kO + c * 8);
        }
        cp_commit();
    };

    float acc[4][4][4];
    #pragma unroll
    for (int i = 0; i < 4; i++)
        #pragma unroll
        for (int j = 0; j < 4; j++)
            #pragma unroll
            for (int r = 0; r < 4; r++) acc[i][j][r] = 0.f;

    issue_stage(0, 0);
    issue_stage(1, 1);
    issue_stage(2, 2);

    const int a_r = lane & 15;
    const int a_c = (lane >> 4) << 3;
    const int b_r = (lane & 7) + ((lane >> 4) << 3);
    const int b_c = ((lane >> 3) & 1) << 3;

    for (int kt = 0; kt < NIT; kt++) {
        cp_wait<2>();
        __syncthreads();
        if (kt + 3 < NIT) issue_stage(kt + 3, (kt + 3) % GSTAGES);
        else cp_commit();

        const int slot = kt % GSTAGES;
        const uint32_t sa = sbase + slot * STG_BYTES;
        const uint32_t sb = sa + STG_A_BYTES;

        #pragma unroll
        for (int ks = 0; ks < 2; ks++) {
            const int kb = ks * 16;
            uint32_t a[4][4];
            #pragma unroll
            for (int i = 0; i < 4; i++)
                ldm_x4(a[i][0], a[i][1], a[i][2], a[i][3],
                       sa + ((wm*64 + i*16 + a_r) * GLD + kb + a_c) * 2);
            uint32_t b[4][2];
            #pragma unroll
            for (int j = 0; j < 2; j++) {
                uint32_t r0, r1, r2, r3;
                ldm_x4(r0, r1, r2, r3,
                       sb + ((wn*32 + j*16 + b_r) * GLD + kb + b_c) * 2);
                b[j*2][0]   = r0; b[j*2][1]   = r1;
                b[j*2+1][0] = r2; b[j*2+1][1] = r3;
            }
            #pragma unroll
            for (int i = 0; i < 4; i++)
                #pragma unroll
                for (int j = 0; j < 4; j++)
                    mma_f16(acc[i][j], a[i], b[j][0], b[j][1]);
        }
    }

    const int cr = lane >> 2;
    const int cc = (lane & 3) * 2;
    #pragma unroll
    for (int j = 0; j < 4; j++) {
        const int col = n0 + wn*32 + j*8 + cc;
        float2 bv = make_float2(0.f, 0.f);
        if (bias) bv = *(const float2*)&bias[col];
        #pragma unroll
        for (int i = 0; i < 4; i++) {
            const int row = m0 + wm*64 + i*16 + cr;
            *(float2*)&C[(size_t)row * N + col] =
                make_float2(acc[i][j][0] + bv.x, acc[i][j][1] + bv.y);
            *(float2*)&C[(size_t)(row + 8) * N + col] =
                make_float2(acc[i][j][2] + bv.x, acc[i][j][3] + bv.y);
        }
    }
}

// ---------------------------------------------------------------------------
// RoPE + scatter -> fp16 hi/lo Q (unscaled), K, V
// ---------------------------------------------------------------------------
__global__ __launch_bounds__(128)
void rope_scatter_kernel(const float* __restrict__ mixed,
                         const float* __restrict__ cache,
                         __half* __restrict__ qh, __half* __restrict__ ql,
                         __half* __restrict__ kh, __half* __restrict__ kl,
                         __half* __restrict__ vh, __half* __restrict__ vl)
{
    const int head = blockIdx.x;
    const int s    = blockIdx.y;
    const int b    = blockIdx.z;
    const int j    = threadIdx.x;

    const float* row = mixed + ((size_t)(b * SQ_ + s)) * QKV_OUT_;

    float out;
    size_t off;
    __half *dh, *dl;
    if (head < NH_ + NG_) {
        const float* x = (head < NH_) ? (row + head * HD_)
                                      : (row + Q_SZ_ + (head - NH_) * HD_);
        if (j < 64) {
            const int p = j >> 1;
            const float x0 = x[2 * p], x1 = x[2 * p + 1];
            const float c0 = cache[((size_t)s * 32 + p) * 2 + 0];
            const float c1 = cache[((size_t)s * 32 + p) * 2 + 1];
            out = (j & 1) ? fmaf(x1, c0, x0 * c1) : fmaf(x0, c0, -x1 * c1);
        } else {
            out = x[j];
        }
        if (head < NH_) {
            off = (((size_t)b * NH_ + head) * SQ_ + s) * HD_ + j;
            dh = qh; dl = ql;
        } else {
            off = (((size_t)b * NG_ + (head - NH_)) * SQ_ + s) * HD_ + j;
            dh = kh; dl = kl;
        }
    } else {
        const int g = head - NH_ - NG_;
        out = row[Q_SZ_ + KV_SZ_ + g * HD_ + j];
        off = (((size_t)b * NG_ + g) * SQ_ + s) * HD_ + j;
        dh = vh; dl = vl;
    }
    __half h = __float2half(out);
    dh[off] = h;
    dl[off] = __float2half(out - __half2float(h));
}

// ---------------------------------------------------------------------------
// Tensor-core flash attention (fp16 hi/lo split, fp32 softmax/accum)
// Scores scaled by 1/sqrt(128) post-MMA. Output -> split-As layout.
// ---------------------------------------------------------------------------
#define FBM 128
#define FBN 64
#define KV_TILE_B (FBN*256)
#define FB_BUF    (4*KV_TILE_B)
#define FLASH2_SMEM (2*FB_BUF)

#define SWZ(row, gr) ((uint32_t)((row)*256 + ((((uint32_t)(gr)) ^ ((row)&7)) << 4)))

__global__ __launch_bounds__(256, 1)
void flash_mma_kernel(const __half* __restrict__ Qh, const __half* __restrict__ Ql,
                      const __half* __restrict__ Kh, const __half* __restrict__ Kl,
                      const __half* __restrict__ Vh, const __half* __restrict__ Vl,
                      __half* __restrict__ As)
{
    extern __shared__ char dsm[];
    const uint32_t sb = smem_u32(dsm);

    const int qb = gridDim.x - 1 - blockIdx.x;
    const int h  = blockIdx.y;
    const int b  = blockIdx.z;
    const int g  = h / REP_;

    const int tid  = threadIdx.x;
    const int lane = tid & 31;
    const int wid  = tid >> 5;
    const int q0   = qb * FBM;
    const int qrow = q0 + wid * 16;
    const int r1   = lane >> 2;
    const int c2   = (lane & 3) * 2;
    const int grp  = lane >> 3;
    const int ri   = lane & 7;

    const float scale = 0.08838834764831845f;

    const __half* Qhp = Qh + ((size_t)b * NH_ + h) * SQ_ * HD_;
    const __half* Qlp = Ql + ((size_t)b * NH_ + h) * SQ_ * HD_;
    const __half* Khp = Kh + ((size_t)b * NG_ + g) * SQ_ * HD_;
    const __half* Klp = Kl + ((size_t)b * NG_ + g) * SQ_ * HD_;
    const __half* Vhp = Vh + ((size_t)b * NG_ + g) * SQ_ * HD_;
    const __half* Vlp = Vl + ((size_t)b * NG_ + g) * SQ_ * HD_;

    uint32_t qfh[8][4], qfl[8][4];
    #pragma unroll
    for (int kc = 0; kc < 8; kc++) {
        const int col = kc * 16 + c2;
        qfh[kc][0] = *(const uint32_t*)&Qhp[(size_t)(qrow + r1)     * HD_ + col];
        qfh[kc][1] = *(const uint32_t*)&Qhp[(size_t)(qrow + r1 + 8) * HD_ + col];
        qfh[kc][2] = *(const uint32_t*)&Qhp[(size_t)(qrow + r1)     * HD_ + col + 8];
        qfh[kc][3] = *(const uint32_t*)&Qhp[(size_t)(qrow + r1 + 8) * HD_ + col + 8];
        qfl[kc][0] = *(const uint32_t*)&Qlp[(size_t)(qrow + r1)     * HD_ + col];
        qfl[kc][1] = *(const uint32_t*)&Qlp[(size_t)(qrow + r1 + 8) * HD_ + col];
        qfl[kc][2] = *(const uint32_t*)&Qlp[(size_t)(qrow + r1)     * HD_ + col + 8];
        qfl[kc][3] = *(const uint32_t*)&Qlp[(size_t)(qrow + r1 + 8) * HD_ + col + 8];
    }

    float o[16][4];
    #pragma unroll
    for (int j = 0; j < 16; j++)
        #pragma unroll
        for (int e = 0; e < 4; e++) o[j][e] = 0.f;
    float m1 = -1e30f, m2 = -1e30f, l1 = 0.f, l2 = 0.f;

    auto issue_kv = [&](int jt, int buf) {
        const uint32_t bbase = sb + (uint32_t)buf * FB_BUF;
        const int s0 = jt * FBN;
        const __half* srcs[4] = {
            Khp + (size_t)s0 * HD_, Klp + (size_t)s0 * HD_,
            Vhp + (size_t)s0 * HD_, Vlp + (size_t)s0 * HD_ };
        #pragma unroll
        for (int t = 0; t < 4; t++) {
            #pragma unroll
            for (int i = 0; i < 4; i++) {
                const int gg = tid + i * 256;
                const int row = gg >> 4, c = gg & 15;
                cp_async16(bbase + t * KV_TILE_B + SWZ(row, c),
                           srcs[t] + (size_t)row * HD_ + c * 8);
            }
        }
        cp_commit();
    };

    const int njt = 2 * qb + 2;
    issue_kv(0, 0);

    for (int jt = 0; jt < njt; jt++) {
        if (jt + 1 < njt) { issue_kv(jt + 1, (jt + 1) & 1); cp_wait<1>(); }
        else              { cp_wait<0>(); }
        __syncthreads();

        const uint32_t bbase = sb + (uint32_t)(jt & 1) * FB_BUF;
        const uint32_t khb = bbase;
        const uint32_t klb = bbase + KV_TILE_B;
        const uint32_t vhb = bbase + 2 * KV_TILE_B;
        const uint32_t vlb = bbase + 3 * KV_TILE_B;

        // ---- S = Q @ K^T ----
        float s[8][4];
        #pragma unroll
        for (int j = 0; j < 8; j++)
            #pragma unroll
            for (int e = 0; e < 4; e++) s[j][e] = 0.f;

        #pragma unroll
        for (int kc = 0; kc < 8; kc++) {
            #pragma unroll
            for (int np = 0; np < 4; np++) {
                const int krow = np * 16 + ri + ((grp >> 1) << 3);
                const int kgr  = 2 * kc + (grp & 1);
                uint32_t h0,h1,h2,h3,l0,l1r,l2r,l3;
                ldm_x4(h0, h1, h2, h3, khb + SWZ(krow, kgr));
                ldm_x4(l0, l1r, l2r, l3, klb + SWZ(krow, kgr));
                mma_f16(s[2*np],   qfh[kc], h0, h1);
                mma_f16(s[2*np+1], qfh[kc], h2, h3);
                mma_f16(s[2*np],   qfl[kc], h0, h1);
                mma_f16(s[2*np+1], qfl[kc], h2, h3);
                mma_f16(s[2*np],   qfh[kc], l0, l1r);
                mma_f16(s[2*np+1], qfh[kc], l2r, l3);
            }
        }

        // scale scores
        #pragma unroll
        for (int j = 0; j < 8; j++)
            #pragma unroll
            for (int e = 0; e < 4; e++) s[j][e] *= scale;

        // ---- causal mask ----
        if (jt >= 2 * qb) {
            const int row1 = qrow + r1, row2 = row1 + 8;
            #pragma unroll
            for (int j = 0; j < 8; j++) {
                const int col = jt * FBN + j * 8 + c2;
                if (col     > row1) s[j][0] = -1e30f;
                if (col + 1 > row1) s[j][1] = -1e30f;
                if (col     > row2) s[j][2] = -1e30f;
                if (col + 1 > row2) s[j][3] = -1e30f;
            }
        }

        // ---- online softmax ----
        float mx1 = -1e30f, mx2 = -1e30f;
        #pragma unroll
        for (int j = 0; j < 8; j++) {
            mx1 = fmaxf(mx1, fmaxf(s[j][0], s[j][1]));
            mx2 = fmaxf(mx2, fmaxf(s[j][2], s[j][3]));
        }
        mx1 = fmaxf(mx1, __shfl_xor_sync(0xffffffffu, mx1, 1));
        mx1 = fmaxf(mx1, __shfl_xor_sync(0xffffffffu, mx1, 2));
        mx2 = fmaxf(mx2, __shfl_xor_sync(0xffffffffu, mx2, 1));
        mx2 = fmaxf(mx2, __shfl_xor_sync(0xffffffffu, mx2, 2));

        const float mn1 = fmaxf(m1, mx1), mn2 = fmaxf(m2, mx2);
        const float a1 = __expf(m1 - mn1), a2 = __expf(m2 - mn2);
        m1 = mn1; m2 = mn2;

        float sum1 = 0.f, sum2 = 0.f;
        #pragma unroll
        for (int j = 0; j < 8; j++) {
            s[j][0] = __expf(s[j][0] - mn1);
            s[j][1] = __expf(s[j][1] - mn1);
            s[j][2] = __expf(s[j][2] - mn2);
            s[j][3] = __expf(s[j][3] - mn2);
            sum1 += s[j][0] + s[j][1];
            sum2 += s[j][2] + s[j][3];
        }
        sum1 += __shfl_xor_sync(0xffffffffu, sum1, 1);
        sum1 += __shfl_xor_sync(0xffffffffu, sum1, 2);
        sum2 += __shfl_xor_sync(0xffffffffu, sum2, 1);
        sum2 += __shfl_xor_sync(0xffffffffu, sum2, 2);
        l1 = l1 * a1 + sum1;
        l2 = l2 * a2 + sum2;

        #pragma unroll
        for (int j = 0; j < 16; j++) {
            o[j][0] *= a1; o[j][1] *= a1;
            o[j][2] *= a2; o[j][3] *= a2;
        }

        // ---- O += P @ V (3-product) ----
        #pragma unroll
        for (int t = 0; t < 4; t++) {
            uint32_t ph[4], pl[4];
            split_pack(ph[0], pl[0], s[2*t][0],   s[2*t][1]);
            split_pack(ph[1], pl[1], s[2*t][2],   s[2*t][3]);
            split_pack(ph[2], pl[2], s[2*t+1][0], s[2*t+1][1]);
            split_pack(ph[3], pl[3], s[2*t+1][2], s[2*t+1][3]);
            #pragma unroll
            for (int np = 0; np < 8; np++) {
                const int vrow = t * 16 + ri + ((grp & 1) << 3);
                const int vgr  = 2 * np + (grp >> 1);
                uint32_t h0,h1,h2,h3,l0,l1r,l2r,l3;
                ldm_x4_t(h0, h1, h2, h3, vhb + SWZ(vrow, vgr));
                ldm_x4_t(l0, l1r, l2r, l3, vlb + SWZ(vrow, vgr));
                mma_f16(o[2*np],   ph, h0, h1);
                mma_f16(o[2*np+1], ph, h2, h3);
                mma_f16(o[2*np],   pl, h0, h1);
                mma_f16(o[2*np+1], pl, h2, h3);
                mma_f16(o[2*np],   ph, l0, l1r);
                mma_f16(o[2*np+1], ph, l2r, l3);
            }
        }
        __syncthreads();
    }

    // ---- epilogue: write split-As layout [hi | lo*2^10 | hi*2^-10] ----
    const float inv1 = 1.f / l1, inv2 = 1.f / l2;
    const size_t mr1 = (size_t)b * SQ_ + qrow + r1;
    const size_t mr2 = mr1 + 8;
    #pragma unroll
    for (int j = 0; j < 16; j++) {
        const int col = h * HD_ + j * 8 + c2;
        {
            const float v0 = o[j][0] * inv1, v1 = o[j][1] * inv1;
            __half h0 = __float2half(v0), h1 = __float2half(v1);
            float f0 = __half2float(h0), f1 = __half2float(h1);
            *(uint32_t*)&As[mr1 * KSPLIT_ + col] = pack_h2(h0, h1);
            *(uint32_t*)&As[mr1 * KSPLIT_ + H_ + col] =
                pack_h2(__float2half((v0 - f0) * SEG_UP), __float2half((v1 - f1) * SEG_UP));
            *(uint32_t*)&As[mr1 * KSPLIT_ + 2*H_ + col] =
                pack_h2(__float2half(f0 * SEG_DN), __float2half(f1 * SEG_DN));
        }
        {
            const float v0 = o[j][2] * inv2, v1 = o[j][3] * inv2;
            __half h0 = __float2half(v0), h1 = __float2half(v1);
            float f0 = __half2float(h0), f1 = __half2float(h1);
            *(uint32_t*)&As[mr2 * KSPLIT_ + col] = pack_h2(h0, h1);
            *(uint32_t*)&As[mr2 * KSPLIT_ + H_ + col] =
                pack_h2(__float2half((v0 - f0) * SEG_UP), __float2half((v1 - f1) * SEG_UP));
            *(uint32_t*)&As[mr2 * KSPLIT_ + 2*H_ + col] =
                pack_h2(__float2half(f0 * SEG_DN), __float2half(f1 * SEG_DN));
        }
    }
}

// ---------------------------------------------------------------------------
// Launch
// ---------------------------------------------------------------------------
extern "C" void kernel_launch(void* const* d_in, const int* in_sizes, int n_in,
                              void* d_out, int out_size)
{
    const float* hidden = (const float*)d_in[0];
    const float* rope   = (const float*)d_in[1];
    const float* Wqkv   = (const float*)d_in[2];
    const float* bqkv   = (const float*)d_in[3];
    const float* Wd     = (const float*)d_in[4];
    float* out = (float*)d_out;

    float* mixed;
    __half *as, *bs, *qh, *ql, *kh, *kl, *vh, *vl;
    cudaGetSymbolAddress((void**)&mixed, g_mixed);
    cudaGetSymbolAddress((void**)&as, g_as);
    cudaGetSymbolAddress((void**)&bs, g_bs);
    cudaGetSymbolAddress((void**)&qh, g_qh);
    cudaGetSymbolAddress((void**)&ql, g_ql);
    cudaGetSymbolAddress((void**)&kh, g_kh);
    cudaGetSymbolAddress((void**)&kl, g_kl);
    cudaGetSymbolAddress((void**)&vh, g_vh);
    cudaGetSymbolAddress((void**)&vl, g_vl);

    cudaFuncSetAttribute(mma_gemm_kernel,
                         cudaFuncAttributeMaxDynamicSharedMemorySize, GEMM_SMEM_BYTES);
    cudaFuncSetAttribute(flash_mma_kernel,
                         cudaFuncAttributeMaxDynamicSharedMemorySize, FLASH2_SMEM);

    const size_t n8 = (size_t)MM_ * H_ / 8;

    // 1) split hidden -> As; transpose+split Wqkv -> Bs
    split_a_kernel<<<(unsigned)((n8 + 255) / 256), 256>>>(hidden, as, H_, n8);
    transpose_split_kernel<<<dim3(QKV_OUT_ / 32, H_ / 32), 256>>>(Wqkv, bs, H_, QKV_OUT_);

    // 2) mixed = hidden @ Wqkv + bias
    mma_gemm_kernel<<<dim3(QKV_OUT_ / GBN, MM_ / GBM), 256, GEMM_SMEM_BYTES>>>(
        as, bs, bqkv, mixed, QKV_OUT_, KSPLIT_);

    // 3) RoPE + scatter -> fp16 hi/lo q/k/v
    rope_scatter_kernel<<<dim3(NH_ + 2 * NG_, SQ_, B_), 128>>>(
        mixed, rope, qh, ql, kh, kl, vh, vl);

    // 4) tensor-core flash attention -> writes split-As directly
    flash_mma_kernel<<<dim3(SQ_ / FBM, NH_, B_), 256, FLASH2_SMEM>>>(
        qh, ql, kh, kl, vh, vl, as);

    // 5) transpose+split Wd -> Bs
    transpose_split_kernel<<<dim3(H_ / 32, H_ / 32), 256>>>(Wd, bs, H_, H_);

    // 6) out = ctx @ Wd
    mma_gemm_kernel<<<dim3(H_ / GBN, MM_ / GBM), 256, GEMM_SMEM_BYTES>>>(
        as, bs, nullptr, out, H_, KSPLIT_);
}

// round 6
// speedup vs baseline: 3.8961x; 1.4255x over previous
#include <cuda_runtime.h>
#include <cuda_fp16.h>
#include <cstdint>
#include <math.h>

// ---------------------------------------------------------------------------
// Problem constants
// ---------------------------------------------------------------------------
#define B_     2
#define SQ_    2048
#define H_     4096
#define NH_    32
#define HD_    128
#define NG_    2
#define QKV_OUT_ (NH_*HD_ + 2*NG_*HD_)   // 4608
#define Q_SZ_    (NH_*HD_)               // 4096
#define KV_SZ_   (NG_*HD_)               // 256
#define REP_     (NH_/NG_)               // 16
#define MM_      (B_*SQ_)                // 4096
#define KSPLIT_  (2*H_)                  // 8192 (2-term K-concat)

// ---------------------------------------------------------------------------
// Scratch
// ---------------------------------------------------------------------------
__device__ float g_mixed[(size_t)MM_*QKV_OUT_];
__device__ __half g_as[(size_t)MM_*KSPLIT_];
__device__ __half g_bs[(size_t)QKV_OUT_*KSPLIT_];
// fp16 hi/lo Q, K; V hi/lo (lo used only for... lo kept for K; V needs hi only,
// but keep vl buffer for S-path symmetry-free code simplicity: NOT loaded in flash)
__device__ __half g_qh[(size_t)B_*NH_*SQ_*HD_];
__device__ __half g_ql[(size_t)B_*NH_*SQ_*HD_];
__device__ __half g_kh[(size_t)B_*NG_*SQ_*HD_];
__device__ __half g_kl[(size_t)B_*NG_*SQ_*HD_];
__device__ __half g_vh[(size_t)B_*NG_*SQ_*HD_];

// ---------------------------------------------------------------------------
// Helpers
// ---------------------------------------------------------------------------
__device__ __forceinline__ uint32_t smem_u32(const void* p) {
    uint32_t a;
    asm("{ .reg .u64 t; cvta.to.shared.u64 t, %1; cvt.u32.u64 %0, t; }" : "=r"(a) : "l"(p));
    return a;
}
__device__ __forceinline__ void cp_async16(uint32_t dst, const void* src) {
    asm volatile("cp.async.cg.shared.global [%0], [%1], 16;" :: "r"(dst), "l"(src));
}
__device__ __forceinline__ void cp_commit() {
    asm volatile("cp.async.commit_group;");
}
template<int N>
__device__ __forceinline__ void cp_wait() {
    asm volatile("cp.async.wait_group %0;" :: "n"(N));
}
__device__ __forceinline__ void ldm_x4(uint32_t& r0, uint32_t& r1, uint32_t& r2,
                                       uint32_t& r3, uint32_t addr) {
    asm volatile("ldmatrix.sync.aligned.m8n8.x4.shared.b16 {%0,%1,%2,%3}, [%4];"
                 : "=r"(r0), "=r"(r1), "=r"(r2), "=r"(r3) : "r"(addr));
}
__device__ __forceinline__ void ldm_x4_t(uint32_t& r0, uint32_t& r1, uint32_t& r2,
                                         uint32_t& r3, uint32_t addr) {
    asm volatile("ldmatrix.sync.aligned.m8n8.x4.trans.shared.b16 {%0,%1,%2,%3}, [%4];"
                 : "=r"(r0), "=r"(r1), "=r"(r2), "=r"(r3) : "r"(addr));
}
__device__ __forceinline__ void mma_f16(float* d, const uint32_t* a,
                                        uint32_t b0, uint32_t b1) {
    asm volatile(
        "mma.sync.aligned.m16n8k16.row.col.f32.f16.f16.f32 "
        "{%0,%1,%2,%3}, {%4,%5,%6,%7}, {%8,%9}, {%0,%1,%2,%3};"
        : "+f"(d[0]), "+f"(d[1]), "+f"(d[2]), "+f"(d[3])
        : "r"(a[0]), "r"(a[1]), "r"(a[2]), "r"(a[3]), "r"(b0), "r"(b1));
}
__device__ __forceinline__ uint32_t pack_h2(__half a, __half b) {
    return (uint32_t)__half_as_ushort(a) | ((uint32_t)__half_as_ushort(b) << 16);
}
__device__ __forceinline__ void split_pack(uint32_t& hi, uint32_t& lo, float p0, float p1) {
    __half h0 = __float2half(p0), h1 = __float2half(p1);
    __half e0 = __float2half(p0 - __half2float(h0));
    __half e1 = __float2half(p1 - __half2float(h1));
    hi = pack_h2(h0, h1);
    lo = pack_h2(e0, e1);
}

// ---------------------------------------------------------------------------
// fp32 -> fp16 2-term split kernels
// ---------------------------------------------------------------------------
// A[M,K] fp32 -> As[M, 2K] fp16, segments [hi | lo]
__global__ __launch_bounds__(256)
void split_a_kernel(const float* __restrict__ A, __half* __restrict__ As,
                    int K, size_t n8)
{
    size_t g = (size_t)blockIdx.x * 256 + threadIdx.x;
    if (g >= n8) return;
    const int kpr = K / 8;
    const size_t m  = g / kpr;
    const int   k8  = (int)(g % kpr) * 8;
    float4 a0 = *(const float4*)&A[m * K + k8];
    float4 a1 = *(const float4*)&A[m * K + k8 + 4];
    float v[8] = {a0.x,a0.y,a0.z,a0.w,a1.x,a1.y,a1.z,a1.w};
    uint32_t hseg[4], lseg[4];
    #pragma unroll
    for (int j = 0; j < 4; j++) {
        __half h0 = __float2half(v[2*j]);
        __half h1 = __float2half(v[2*j+1]);
        hseg[j] = pack_h2(h0, h1);
        lseg[j] = pack_h2(__float2half(v[2*j]   - __half2float(h0)),
                          __float2half(v[2*j+1] - __half2float(h1)));
    }
    __half* row = As + m * (size_t)(2*K);
    *(uint4*)&row[k8]     = *(uint4*)hseg;
    *(uint4*)&row[K + k8] = *(uint4*)lseg;
}

// W[K,N] fp32 -> Bs[N, 2K] fp16 (transposed), segments [hi | hi]
__global__ __launch_bounds__(256)
void transpose_split_kernel(const float* __restrict__ W, __half* __restrict__ Bs,
                            int K, int N)
{
    __shared__ float t[32][33];
    const int n0 = blockIdx.x * 32, k0 = blockIdx.y * 32;
    const int tx = threadIdx.x & 31, ty = threadIdx.x >> 5;
    #pragma unroll
    for (int i = 0; i < 4; i++)
        t[ty + 8*i][tx] = W[(size_t)(k0 + ty + 8*i) * N + n0 + tx];
    __syncthreads();
    #pragma unroll
    for (int i = 0; i < 4; i++) {
        float v = t[tx][ty + 8*i];
        __half h = __float2half(v);
        __half* row = Bs + (size_t)(n0 + ty + 8*i) * (2*K);
        row[k0 + tx]     = h;
        row[K + k0 + tx] = h;
    }
}

// ---------------------------------------------------------------------------
// fp16 tensor-core GEMM: C[M,N] = As[M,K'] @ Bs[N,K']^T  (K' = 8192)
// BM=BN=128, BK=32, 8 warps, 4-stage cp.async pipeline.
// ---------------------------------------------------------------------------
#define GBM 128
#define GBN 128
#define GBK 32
#define GLD 40
#define STG_A_BYTES (GBM*GLD*2)
#define STG_BYTES   ((GBM+GBN)*GLD*2)
#define GSTAGES 4
#define GEMM_SMEM_BYTES (GSTAGES*STG_BYTES)   // 81920

__global__ __launch_bounds__(256)
void mma_gemm_kernel(const __half* __restrict__ Ag,
                     const __half* __restrict__ Bg,
                     const float* __restrict__ bias, float* __restrict__ C,
                     int N, int Kp)
{
    extern __shared__ char dsm[];
    const uint32_t sbase = smem_u32(dsm);

    const int tid  = threadIdx.x;
    const int lane = tid & 31;
    const int wid  = tid >> 5;
    const int wm   = wid >> 2;
    const int wn   = wid & 3;
    const int m0   = blockIdx.y * GBM;
    const int n0   = blockIdx.x * GBN;

    const __half* Arow = Ag + (size_t)m0 * Kp;
    const __half* Brow = Bg + (size_t)n0 * Kp;

    const int NIT = Kp / GBK;

    auto issue_stage = [&](int kt, int slot) {
        const uint32_t sa = sbase + slot * STG_BYTES;
        const uint32_t sb = sa + STG_A_BYTES;
        const int kO = kt * GBK;
        #pragma unroll
        for (int h = 0; h < 2; h++) {
            const int g = tid + h * 256;
            const int r = g >> 2, c = g & 3;
            cp_async16(sa + (r * GLD + c * 8) * 2,
                       Arow + (size_t)r * Kp + kO + c * 8);
            cp_async16(sb + (r * GLD + c * 8) * 2,
                       Brow + (size_t)r * Kp + kO + c * 8);
        }
        cp_commit();
    };

    float acc[4][4][4];
    #pragma unroll
    for (int i = 0; i < 4; i++)
        #pragma unroll
        for (int j = 0; j < 4; j++)
            #pragma unroll
            for (int r = 0; r < 4; r++) acc[i][j][r] = 0.f;

    issue_stage(0, 0);
    issue_stage(1, 1);
    issue_stage(2, 2);

    const int a_r = lane & 15;
    const int a_c = (lane >> 4) << 3;
    const int b_r = (lane & 7) + ((lane >> 4) << 3);
    const int b_c = ((lane >> 3) & 1) << 3;

    for (int kt = 0; kt < NIT; kt++) {
        cp_wait<2>();
        __syncthreads();
        if (kt + 3 < NIT) issue_stage(kt + 3, (kt + 3) % GSTAGES);
        else cp_commit();

        const int slot = kt % GSTAGES;
        const uint32_t sa = sbase + slot * STG_BYTES;
        const uint32_t sb = sa + STG_A_BYTES;

        #pragma unroll
        for (int ks = 0; ks < 2; ks++) {
            const int kb = ks * 16;
            uint32_t a[4][4];
            #pragma unroll
            for (int i = 0; i < 4; i++)
                ldm_x4(a[i][0], a[i][1], a[i][2], a[i][3],
                       sa + ((wm*64 + i*16 + a_r) * GLD + kb + a_c) * 2);
            uint32_t b[4][2];
            #pragma unroll
            for (int j = 0; j < 2; j++) {
                uint32_t r0, r1, r2, r3;
                ldm_x4(r0, r1, r2, r3,
                       sb + ((wn*32 + j*16 + b_r) * GLD + kb + b_c) * 2);
                b[j*2][0]   = r0; b[j*2][1]   = r1;
                b[j*2+1][0] = r2; b[j*2+1][1] = r3;
            }
            #pragma unroll
            for (int i = 0; i < 4; i++)
                #pragma unroll
                for (int j = 0; j < 4; j++)
                    mma_f16(acc[i][j], a[i], b[j][0], b[j][1]);
        }
    }

    const int cr = lane >> 2;
    const int cc = (lane & 3) * 2;
    #pragma unroll
    for (int j = 0; j < 4; j++) {
        const int col = n0 + wn*32 + j*8 + cc;
        float2 bv = make_float2(0.f, 0.f);
        if (bias) bv = *(const float2*)&bias[col];
        #pragma unroll
        for (int i = 0; i < 4; i++) {
            const int row = m0 + wm*64 + i*16 + cr;
            *(float2*)&C[(size_t)row * N + col] =
                make_float2(acc[i][j][0] + bv.x, acc[i][j][1] + bv.y);
            *(float2*)&C[(size_t)(row + 8) * N + col] =
                make_float2(acc[i][j][2] + bv.x, acc[i][j][3] + bv.y);
        }
    }
}

// ---------------------------------------------------------------------------
// RoPE + scatter -> fp16 hi/lo Q, K; hi-only V
// ---------------------------------------------------------------------------
__global__ __launch_bounds__(128)
void rope_scatter_kernel(const float* __restrict__ mixed,
                         const float* __restrict__ cache,
                         __half* __restrict__ qh, __half* __restrict__ ql,
                         __half* __restrict__ kh, __half* __restrict__ kl,
                         __half* __restrict__ vh)
{
    const int head = blockIdx.x;
    const int s    = blockIdx.y;
    const int b    = blockIdx.z;
    const int j    = threadIdx.x;

    const float* row = mixed + ((size_t)(b * SQ_ + s)) * QKV_OUT_;

    if (head < NH_ + NG_) {
        const float* x = (head < NH_) ? (row + head * HD_)
                                      : (row + Q_SZ_ + (head - NH_) * HD_);
        float out;
        if (j < 64) {
            const int p = j >> 1;
            const float x0 = x[2 * p], x1 = x[2 * p + 1];
            const float c0 = cache[((size_t)s * 32 + p) * 2 + 0];
            const float c1 = cache[((size_t)s * 32 + p) * 2 + 1];
            out = (j & 1) ? fmaf(x1, c0, x0 * c1) : fmaf(x0, c0, -x1 * c1);
        } else {
            out = x[j];
        }
        size_t off;
        __half *dh, *dl;
        if (head < NH_) {
            off = (((size_t)b * NH_ + head) * SQ_ + s) * HD_ + j;
            dh = qh; dl = ql;
        } else {
            off = (((size_t)b * NG_ + (head - NH_)) * SQ_ + s) * HD_ + j;
            dh = kh; dl = kl;
        }
        __half h = __float2half(out);
        dh[off] = h;
        dl[off] = __float2half(out - __half2float(h));
    } else {
        const int g = head - NH_ - NG_;
        const float out = row[Q_SZ_ + KV_SZ_ + g * HD_ + j];
        vh[(((size_t)b * NG_ + g) * SQ_ + s) * HD_ + j] = __float2half(out);
    }
}

// ---------------------------------------------------------------------------
// Tensor-core flash attention
// S-path: 3-term (QhKh + QlKh + QhKl). PV-path: 2-term ((Ph+Pl)·Vh).
// Buffers per stage: Kh, Kl, Vh (48 KB); double-buffered (96 KB).
// ---------------------------------------------------------------------------
#define FBM 128
#define FBN 64
#define KV_TILE_B (FBN*256)          // 16 KB
#define FB_BUF    (3*KV_TILE_B)      // Kh, Kl, Vh
#define FLASH2_SMEM (2*FB_BUF)       // 96 KB

#define SWZ(row, gr) ((uint32_t)((row)*256 + ((((uint32_t)(gr)) ^ ((row)&7)) << 4)))

__global__ __launch_bounds__(256, 1)
void flash_mma_kernel(const __half* __restrict__ Qh, const __half* __restrict__ Ql,
                      const __half* __restrict__ Kh, const __half* __restrict__ Kl,
                      const __half* __restrict__ Vh,
                      __half* __restrict__ As)
{
    extern __shared__ char dsm[];
    const uint32_t sb = smem_u32(dsm);

    const int qb = gridDim.x - 1 - blockIdx.x;
    const int h  = blockIdx.y;
    const int b  = blockIdx.z;
    const int g  = h / REP_;

    const int tid  = threadIdx.x;
    const int lane = tid & 31;
    const int wid  = tid >> 5;
    const int q0   = qb * FBM;
    const int qrow = q0 + wid * 16;
    const int r1   = lane >> 2;
    const int c2   = (lane & 3) * 2;
    const int grp  = lane >> 3;
    const int ri   = lane & 7;

    const float scale = 0.08838834764831845f;

    const __half* Qhp = Qh + ((size_t)b * NH_ + h) * SQ_ * HD_;
    const __half* Qlp = Ql + ((size_t)b * NH_ + h) * SQ_ * HD_;
    const __half* Khp = Kh + ((size_t)b * NG_ + g) * SQ_ * HD_;
    const __half* Klp = Kl + ((size_t)b * NG_ + g) * SQ_ * HD_;
    const __half* Vhp = Vh + ((size_t)b * NG_ + g) * SQ_ * HD_;

    uint32_t qfh[8][4], qfl[8][4];
    #pragma unroll
    for (int kc = 0; kc < 8; kc++) {
        const int col = kc * 16 + c2;
        qfh[kc][0] = *(const uint32_t*)&Qhp[(size_t)(qrow + r1)     * HD_ + col];
        qfh[kc][1] = *(const uint32_t*)&Qhp[(size_t)(qrow + r1 + 8) * HD_ + col];
        qfh[kc][2] = *(const uint32_t*)&Qhp[(size_t)(qrow + r1)     * HD_ + col + 8];
        qfh[kc][3] = *(const uint32_t*)&Qhp[(size_t)(qrow + r1 + 8) * HD_ + col + 8];
        qfl[kc][0] = *(const uint32_t*)&Qlp[(size_t)(qrow + r1)     * HD_ + col];
        qfl[kc][1] = *(const uint32_t*)&Qlp[(size_t)(qrow + r1 + 8) * HD_ + col];
        qfl[kc][2] = *(const uint32_t*)&Qlp[(size_t)(qrow + r1)     * HD_ + col + 8];
        qfl[kc][3] = *(const uint32_t*)&Qlp[(size_t)(qrow + r1 + 8) * HD_ + col + 8];
    }

    float o[16][4];
    #pragma unroll
    for (int j = 0; j < 16; j++)
        #pragma unroll
        for (int e = 0; e < 4; e++) o[j][e] = 0.f;
    float m1 = -1e30f, m2 = -1e30f, l1 = 0.f, l2 = 0.f;

    auto issue_kv = [&](int jt, int buf) {
        const uint32_t bbase = sb + (uint32_t)buf * FB_BUF;
        const int s0 = jt * FBN;
        const __half* srcs[3] = {
            Khp + (size_t)s0 * HD_, Klp + (size_t)s0 * HD_,
            Vhp + (size_t)s0 * HD_ };
        #pragma unroll
        for (int t = 0; t < 3; t++) {
            #pragma unroll
            for (int i = 0; i < 4; i++) {
                const int gg = tid + i * 256;
                const int row = gg >> 4, c = gg & 15;
                cp_async16(bbase + t * KV_TILE_B + SWZ(row, c),
                           srcs[t] + (size_t)row * HD_ + c * 8);
            }
        }
        cp_commit();
    };

    const int njt = 2 * qb + 2;
    issue_kv(0, 0);

    for (int jt = 0; jt < njt; jt++) {
        if (jt + 1 < njt) { issue_kv(jt + 1, (jt + 1) & 1); cp_wait<1>(); }
        else              { cp_wait<0>(); }
        __syncthreads();

        const uint32_t bbase = sb + (uint32_t)(jt & 1) * FB_BUF;
        const uint32_t khb = bbase;
        const uint32_t klb = bbase + KV_TILE_B;
        const uint32_t vhb = bbase + 2 * KV_TILE_B;

        // ---- S = Q @ K^T (3-term) ----
        float s[8][4];
        #pragma unroll
        for (int j = 0; j < 8; j++)
            #pragma unroll
            for (int e = 0; e < 4; e++) s[j][e] = 0.f;

        #pragma unroll
        for (int kc = 0; kc < 8; kc++) {
            #pragma unroll
            for (int np = 0; np < 4; np++) {
                const int krow = np * 16 + ri + ((grp >> 1) << 3);
                const int kgr  = 2 * kc + (grp & 1);
                uint32_t h0,h1,h2,h3,l0,l1r,l2r,l3;
                ldm_x4(h0, h1, h2, h3, khb + SWZ(krow, kgr));
                ldm_x4(l0, l1r, l2r, l3, klb + SWZ(krow, kgr));
                mma_f16(s[2*np],   qfh[kc], h0, h1);
                mma_f16(s[2*np+1], qfh[kc], h2, h3);
                mma_f16(s[2*np],   qfl[kc], h0, h1);
                mma_f16(s[2*np+1], qfl[kc], h2, h3);
                mma_f16(s[2*np],   qfh[kc], l0, l1r);
                mma_f16(s[2*np+1], qfh[kc], l2r, l3);
            }
        }

        // scale scores
        #pragma unroll
        for (int j = 0; j < 8; j++)
            #pragma unroll
            for (int e = 0; e < 4; e++) s[j][e] *= scale;

        // ---- causal mask ----
        if (jt >= 2 * qb) {
            const int row1 = qrow + r1, row2 = row1 + 8;
            #pragma unroll
            for (int j = 0; j < 8; j++) {
                const int col = jt * FBN + j * 8 + c2;
                if (col     > row1) s[j][0] = -1e30f;
                if (col + 1 > row1) s[j][1] = -1e30f;
                if (col     > row2) s[j][2] = -1e30f;
                if (col + 1 > row2) s[j][3] = -1e30f;
            }
        }

        // ---- online softmax ----
        float mx1 = -1e30f, mx2 = -1e30f;
        #pragma unroll
        for (int j = 0; j < 8; j++) {
            mx1 = fmaxf(mx1, fmaxf(s[j][0], s[j][1]));
            mx2 = fmaxf(mx2, fmaxf(s[j][2], s[j][3]));
        }
        mx1 = fmaxf(mx1, __shfl_xor_sync(0xffffffffu, mx1, 1));
        mx1 = fmaxf(mx1, __shfl_xor_sync(0xffffffffu, mx1, 2));
        mx2 = fmaxf(mx2, __shfl_xor_sync(0xffffffffu, mx2, 1));
        mx2 = fmaxf(mx2, __shfl_xor_sync(0xffffffffu, mx2, 2));

        const float mn1 = fmaxf(m1, mx1), mn2 = fmaxf(m2, mx2);
        const float a1 = __expf(m1 - mn1), a2 = __expf(m2 - mn2);
        m1 = mn1; m2 = mn2;

        float sum1 = 0.f, sum2 = 0.f;
        #pragma unroll
        for (int j = 0; j < 8; j++) {
            s[j][0] = __expf(s[j][0] - mn1);
            s[j][1] = __expf(s[j][1] - mn1);
            s[j][2] = __expf(s[j][2] - mn2);
            s[j][3] = __expf(s[j][3] - mn2);
            sum1 += s[j][0] + s[j][1];
            sum2 += s[j][2] + s[j][3];
        }
        sum1 += __shfl_xor_sync(0xffffffffu, sum1, 1);
        sum1 += __shfl_xor_sync(0xffffffffu, sum1, 2);
        sum2 += __shfl_xor_sync(0xffffffffu, sum2, 1);
        sum2 += __shfl_xor_sync(0xffffffffu, sum2, 2);
        l1 = l1 * a1 + sum1;
        l2 = l2 * a2 + sum2;

        #pragma unroll
        for (int j = 0; j < 16; j++) {
            o[j][0] *= a1; o[j][1] *= a1;
            o[j][2] *= a2; o[j][3] *= a2;
        }

        // ---- O += P @ V (2-term: (Ph+Pl)·Vh) ----
        #pragma unroll
        for (int t = 0; t < 4; t++) {
            uint32_t ph[4], pl[4];
            split_pack(ph[0], pl[0], s[2*t][0],   s[2*t][1]);
            split_pack(ph[1], pl[1], s[2*t][2],   s[2*t][3]);
            split_pack(ph[2], pl[2], s[2*t+1][0], s[2*t+1][1]);
            split_pack(ph[3], pl[3], s[2*t+1][2], s[2*t+1][3]);
            #pragma unroll
            for (int np = 0; np < 8; np++) {
                const int vrow = t * 16 + ri + ((grp & 1) << 3);
                const int vgr  = 2 * np + (grp >> 1);
                uint32_t h0,h1,h2,h3;
                ldm_x4_t(h0, h1, h2, h3, vhb + SWZ(vrow, vgr));
                mma_f16(o[2*np],   ph, h0, h1);
                mma_f16(o[2*np+1], ph, h2, h3);
                mma_f16(o[2*np],   pl, h0, h1);
                mma_f16(o[2*np+1], pl, h2, h3);
            }
        }
        __syncthreads();
    }

    // ---- epilogue: write split-As 2-term layout [hi | lo] ----
    const float inv1 = 1.f / l1, inv2 = 1.f / l2;
    const size_t mr1 = (size_t)b * SQ_ + qrow + r1;
    const size_t mr2 = mr1 + 8;
    #pragma unroll
    for (int j = 0; j < 16; j++) {
        const int col = h * HD_ + j * 8 + c2;
        uint32_t hi, lo;
        split_pack(hi, lo, o[j][0] * inv1, o[j][1] * inv1);
        *(uint32_t*)&As[mr1 * KSPLIT_ + col]      = hi;
        *(uint32_t*)&As[mr1 * KSPLIT_ + H_ + col] = lo;
        split_pack(hi, lo, o[j][2] * inv2, o[j][3] * inv2);
        *(uint32_t*)&As[mr2 * KSPLIT_ + col]      = hi;
        *(uint32_t*)&As[mr2 * KSPLIT_ + H_ + col] = lo;
    }
}

// ---------------------------------------------------------------------------
// Launch
// ---------------------------------------------------------------------------
extern "C" void kernel_launch(void* const* d_in, const int* in_sizes, int n_in,
                              void* d_out, int out_size)
{
    const float* hidden = (const float*)d_in[0];
    const float* rope   = (const float*)d_in[1];
    const float* Wqkv   = (const float*)d_in[2];
    const float* bqkv   = (const float*)d_in[3];
    const float* Wd     = (const float*)d_in[4];
    float* out = (float*)d_out;

    float* mixed;
    __half *as, *bs, *qh, *ql, *kh, *kl, *vh;
    cudaGetSymbolAddress((void**)&mixed, g_mixed);
    cudaGetSymbolAddress((void**)&as, g_as);
    cudaGetSymbolAddress((void**)&bs, g_bs);
    cudaGetSymbolAddress((void**)&qh, g_qh);
    cudaGetSymbolAddress((void**)&ql, g_ql);
    cudaGetSymbolAddress((void**)&kh, g_kh);
    cudaGetSymbolAddress((void**)&kl, g_kl);
    cudaGetSymbolAddress((void**)&vh, g_vh);

    cudaFuncSetAttribute(mma_gemm_kernel,
                         cudaFuncAttributeMaxDynamicSharedMemorySize, GEMM_SMEM_BYTES);
    cudaFuncSetAttribute(flash_mma_kernel,
                         cudaFuncAttributeMaxDynamicSharedMemorySize, FLASH2_SMEM);

    const size_t n8 = (size_t)MM_ * H_ / 8;

    // 1) split hidden -> As [M, 2K]; transpose+split Wqkv -> Bs [4608, 2K]
    split_a_kernel<<<(unsigned)((n8 + 255) / 256), 256>>>(hidden, as, H_, n8);
    transpose_split_kernel<<<dim3(QKV_OUT_ / 32, H_ / 32), 256>>>(Wqkv, bs, H_, QKV_OUT_);

    // 2) mixed = hidden @ Wqkv + bias
    mma_gemm_kernel<<<dim3(QKV_OUT_ / GBN, MM_ / GBM), 256, GEMM_SMEM_BYTES>>>(
        as, bs, bqkv, mixed, QKV_OUT_, KSPLIT_);

    // 3) RoPE + scatter -> fp16 hi/lo q/k, hi v
    rope_scatter_kernel<<<dim3(NH_ + 2 * NG_, SQ_, B_), 128>>>(
        mixed, rope, qh, ql, kh, kl, vh);

    // 4) tensor-core flash attention -> writes split-As directly
    flash_mma_kernel<<<dim3(SQ_ / FBM, NH_, B_), 256, FLASH2_SMEM>>>(
        qh, ql, kh, kl, vh, as);

    // 5) transpose+split Wd -> Bs [4096, 2K]
    transpose_split_kernel<<<dim3(H_ / 32, H_ / 32), 256>>>(Wd, bs, H_, H_);

    // 6) out = ctx @ Wd
    mma_gemm_kernel<<<dim3(H_ / GBN, MM_ / GBM), 256, GEMM_SMEM_BYTES>>>(
        as, bs, nullptr, out, H_, KSPLIT_);
}

// round 7
// speedup vs baseline: 4.0475x; 1.0388x over previous
#include <cuda_runtime.h>
#include <cuda_fp16.h>
#include <cstdint>
#include <math.h>

// ---------------------------------------------------------------------------
// Problem constants
// ---------------------------------------------------------------------------
#define B_     2
#define SQ_    2048
#define H_     4096
#define NH_    32
#define HD_    128
#define NG_    2
#define QKV_OUT_ (NH_*HD_ + 2*NG_*HD_)   // 4608
#define Q_SZ_    (NH_*HD_)               // 4096
#define KV_SZ_   (NG_*HD_)               // 256
#define REP_     (NH_/NG_)               // 16
#define MM_      (B_*SQ_)                // 4096
#define KSPLIT_  (2*H_)                  // 8192 (2-term K-concat)

// ---------------------------------------------------------------------------
// Scratch
// ---------------------------------------------------------------------------
__device__ __half g_as[(size_t)MM_*KSPLIT_];
__device__ __half g_bs[(size_t)QKV_OUT_*KSPLIT_];
__device__ __half g_qh[(size_t)B_*NH_*SQ_*HD_];
__device__ __half g_ql[(size_t)B_*NH_*SQ_*HD_];
__device__ __half g_kh[(size_t)B_*NG_*SQ_*HD_];
__device__ __half g_kl[(size_t)B_*NG_*SQ_*HD_];
__device__ __half g_vh[(size_t)B_*NG_*SQ_*HD_];

// ---------------------------------------------------------------------------
// Helpers
// ---------------------------------------------------------------------------
__device__ __forceinline__ uint32_t smem_u32(const void* p) {
    uint32_t a;
    asm("{ .reg .u64 t; cvta.to.shared.u64 t, %1; cvt.u32.u64 %0, t; }" : "=r"(a) : "l"(p));
    return a;
}
__device__ __forceinline__ void cp_async16(uint32_t dst, const void* src) {
    asm volatile("cp.async.cg.shared.global [%0], [%1], 16;" :: "r"(dst), "l"(src));
}
__device__ __forceinline__ void cp_commit() {
    asm volatile("cp.async.commit_group;");
}
template<int N>
__device__ __forceinline__ void cp_wait() {
    asm volatile("cp.async.wait_group %0;" :: "n"(N));
}
__device__ __forceinline__ void ldm_x4(uint32_t& r0, uint32_t& r1, uint32_t& r2,
                                       uint32_t& r3, uint32_t addr) {
    asm volatile("ldmatrix.sync.aligned.m8n8.x4.shared.b16 {%0,%1,%2,%3}, [%4];"
                 : "=r"(r0), "=r"(r1), "=r"(r2), "=r"(r3) : "r"(addr));
}
__device__ __forceinline__ void ldm_x4_t(uint32_t& r0, uint32_t& r1, uint32_t& r2,
                                         uint32_t& r3, uint32_t addr) {
    asm volatile("ldmatrix.sync.aligned.m8n8.x4.trans.shared.b16 {%0,%1,%2,%3}, [%4];"
                 : "=r"(r0), "=r"(r1), "=r"(r2), "=r"(r3) : "r"(addr));
}
__device__ __forceinline__ void mma_f16(float* d, const uint32_t* a,
                                        uint32_t b0, uint32_t b1) {
    asm volatile(
        "mma.sync.aligned.m16n8k16.row.col.f32.f16.f16.f32 "
        "{%0,%1,%2,%3}, {%4,%5,%6,%7}, {%8,%9}, {%0,%1,%2,%3};"
        : "+f"(d[0]), "+f"(d[1]), "+f"(d[2]), "+f"(d[3])
        : "r"(a[0]), "r"(a[1]), "r"(a[2]), "r"(a[3]), "r"(b0), "r"(b1));
}
__device__ __forceinline__ uint32_t pack_h2(__half a, __half b) {
    return (uint32_t)__half_as_ushort(a) | ((uint32_t)__half_as_ushort(b) << 16);
}
__device__ __forceinline__ void split_pack(uint32_t& hi, uint32_t& lo, float p0, float p1) {
    __half h0 = __float2half(p0), h1 = __float2half(p1);
    __half e0 = __float2half(p0 - __half2float(h0));
    __half e1 = __float2half(p1 - __half2float(h1));
    hi = pack_h2(h0, h1);
    lo = pack_h2(e0, e1);
}

// ---------------------------------------------------------------------------
// fp32 -> fp16 2-term split kernels
// ---------------------------------------------------------------------------
__global__ __launch_bounds__(256)
void split_a_kernel(const float* __restrict__ A, __half* __restrict__ As,
                    int K, size_t n8)
{
    size_t g = (size_t)blockIdx.x * 256 + threadIdx.x;
    if (g >= n8) return;
    const int kpr = K / 8;
    const size_t m  = g / kpr;
    const int   k8  = (int)(g % kpr) * 8;
    float4 a0 = *(const float4*)&A[m * K + k8];
    float4 a1 = *(const float4*)&A[m * K + k8 + 4];
    float v[8] = {a0.x,a0.y,a0.z,a0.w,a1.x,a1.y,a1.z,a1.w};
    uint32_t hseg[4], lseg[4];
    #pragma unroll
    for (int j = 0; j < 4; j++) {
        __half h0 = __float2half(v[2*j]);
        __half h1 = __float2half(v[2*j+1]);
        hseg[j] = pack_h2(h0, h1);
        lseg[j] = pack_h2(__float2half(v[2*j]   - __half2float(h0)),
                          __float2half(v[2*j+1] - __half2float(h1)));
    }
    __half* row = As + m * (size_t)(2*K);
    *(uint4*)&row[k8]     = *(uint4*)hseg;
    *(uint4*)&row[K + k8] = *(uint4*)lseg;
}

__global__ __launch_bounds__(256)
void transpose_split_kernel(const float* __restrict__ W, __half* __restrict__ Bs,
                            int K, int N)
{
    __shared__ float t[32][33];
    const int n0 = blockIdx.x * 32, k0 = blockIdx.y * 32;
    const int tx = threadIdx.x & 31, ty = threadIdx.x >> 5;
    #pragma unroll
    for (int i = 0; i < 4; i++)
        t[ty + 8*i][tx] = W[(size_t)(k0 + ty + 8*i) * N + n0 + tx];
    __syncthreads();
    #pragma unroll
    for (int i = 0; i < 4; i++) {
        float v = t[tx][ty + 8*i];
        __half h = __float2half(v);
        __half* row = Bs + (size_t)(n0 + ty + 8*i) * (2*K);
        row[k0 + tx]     = h;
        row[K + k0 + tx] = h;
    }
}

// ---------------------------------------------------------------------------
// fp16 tensor-core GEMM. MODE 0: fp32 C store. MODE 1: fused bias + RoPE +
// fp16 hi/lo split + q/k/v scatter (QKV GEMM; one head per CTA col-block).
// ---------------------------------------------------------------------------
#define GBM 128
#define GBN 128
#define GBK 32
#define GLD 40
#define STG_A_BYTES (GBM*GLD*2)
#define STG_BYTES   ((GBM+GBN)*GLD*2)
#define GSTAGES 4
#define GEMM_SMEM_BYTES (GSTAGES*STG_BYTES)   // 81920

template<int MODE>
__global__ __launch_bounds__(256)
void mma_gemm_kernel(const __half* __restrict__ Ag,
                     const __half* __restrict__ Bg,
                     const float* __restrict__ bias,
                     const float* __restrict__ cache,
                     float* __restrict__ C,
                     __half* __restrict__ qh, __half* __restrict__ ql,
                     __half* __restrict__ kh, __half* __restrict__ kl,
                     __half* __restrict__ vh,
                     int N, int Kp)
{
    extern __shared__ char dsm[];
    const uint32_t sbase = smem_u32(dsm);

    const int tid  = threadIdx.x;
    const int lane = tid & 31;
    const int wid  = tid >> 5;
    const int wm   = wid >> 2;
    const int wn   = wid & 3;
    const int m0   = blockIdx.y * GBM;
    const int n0   = blockIdx.x * GBN;

    const __half* Arow = Ag + (size_t)m0 * Kp;
    const __half* Brow = Bg + (size_t)n0 * Kp;

    const int NIT = Kp / GBK;

    auto issue_stage = [&](int kt, int slot) {
        const uint32_t sa = sbase + slot * STG_BYTES;
        const uint32_t sb = sa + STG_A_BYTES;
        const int kO = kt * GBK;
        #pragma unroll
        for (int h = 0; h < 2; h++) {
            const int g = tid + h * 256;
            const int r = g >> 2, c = g & 3;
            cp_async16(sa + (r * GLD + c * 8) * 2,
                       Arow + (size_t)r * Kp + kO + c * 8);
            cp_async16(sb + (r * GLD + c * 8) * 2,
                       Brow + (size_t)r * Kp + kO + c * 8);
        }
        cp_commit();
    };

    float acc[4][4][4];
    #pragma unroll
    for (int i = 0; i < 4; i++)
        #pragma unroll
        for (int j = 0; j < 4; j++)
            #pragma unroll
            for (int r = 0; r < 4; r++) acc[i][j][r] = 0.f;

    issue_stage(0, 0);
    issue_stage(1, 1);
    issue_stage(2, 2);

    const int a_r = lane & 15;
    const int a_c = (lane >> 4) << 3;
    const int b_r = (lane & 7) + ((lane >> 4) << 3);
    const int b_c = ((lane >> 3) & 1) << 3;

    for (int kt = 0; kt < NIT; kt++) {
        cp_wait<2>();
        __syncthreads();
        if (kt + 3 < NIT) issue_stage(kt + 3, (kt + 3) % GSTAGES);
        else cp_commit();

        const int slot = kt % GSTAGES;
        const uint32_t sa = sbase + slot * STG_BYTES;
        const uint32_t sb = sa + STG_A_BYTES;

        #pragma unroll
        for (int ks = 0; ks < 2; ks++) {
            const int kb = ks * 16;
            uint32_t a[4][4];
            #pragma unroll
            for (int i = 0; i < 4; i++)
                ldm_x4(a[i][0], a[i][1], a[i][2], a[i][3],
                       sa + ((wm*64 + i*16 + a_r) * GLD + kb + a_c) * 2);
            uint32_t b[4][2];
            #pragma unroll
            for (int j = 0; j < 2; j++) {
                uint32_t r0, r1, r2, r3;
                ldm_x4(r0, r1, r2, r3,
                       sb + ((wn*32 + j*16 + b_r) * GLD + kb + b_c) * 2);
                b[j*2][0]   = r0; b[j*2][1]   = r1;
                b[j*2+1][0] = r2; b[j*2+1][1] = r3;
            }
            #pragma unroll
            for (int i = 0; i < 4; i++)
                #pragma unroll
                for (int j = 0; j < 4; j++)
                    mma_f16(acc[i][j], a[i], b[j][0], b[j][1]);
        }
    }

    const int cr = lane >> 2;
    const int cc = (lane & 3) * 2;

    if (MODE == 0) {
        #pragma unroll
        for (int j = 0; j < 4; j++) {
            const int col = n0 + wn*32 + j*8 + cc;
            #pragma unroll
            for (int i = 0; i < 4; i++) {
                const int row = m0 + wm*64 + i*16 + cr;
                *(float2*)&C[(size_t)row * N + col] =
                    make_float2(acc[i][j][0], acc[i][j][1]);
                *(float2*)&C[(size_t)(row + 8) * N + col] =
                    make_float2(acc[i][j][2], acc[i][j][3]);
            }
        }
    } else {
        // Fused bias + RoPE + split + scatter. One head per CTA col-block.
        const int hidx = n0 >> 7;            // 0..35
        #pragma unroll
        for (int j = 0; j < 4; j++) {
            const int d   = wn*32 + j*8 + cc;         // 0..126 (even), within head
            const float2 bv = *(const float2*)&bias[n0 + d];
            const bool rot = (d < 64);
            const int p = d >> 1;
            #pragma unroll
            for (int i = 0; i < 4; i++) {
                #pragma unroll
                for (int hrw = 0; hrw < 2; hrw++) {
                    const int row = m0 + wm*64 + i*16 + cr + hrw*8;
                    float x0 = acc[i][j][hrw*2+0] + bv.x;
                    float x1 = acc[i][j][hrw*2+1] + bv.y;
                    const int bb = row >> 11;          // /SQ_
                    const int s  = row & (SQ_ - 1);
                    if (hidx < NH_ + NG_ && rot) {
                        const float2 c = *(const float2*)&cache[((size_t)s * 32 + p) * 2];
                        const float o0 = x0 * c.x - x1 * c.y;
                        const float o1 = x1 * c.x + x0 * c.y;
                        x0 = o0; x1 = o1;
                    }
                    uint32_t hi, lo;
                    if (hidx < NH_) {
                        split_pack(hi, lo, x0, x1);
                        const size_t off = (((size_t)bb * NH_ + hidx) * SQ_ + s) * HD_ + d;
                        *(uint32_t*)&qh[off] = hi;
                        *(uint32_t*)&ql[off] = lo;
                    } else if (hidx < NH_ + NG_) {
                        split_pack(hi, lo, x0, x1);
                        const size_t off = (((size_t)bb * NG_ + (hidx - NH_)) * SQ_ + s) * HD_ + d;
                        *(uint32_t*)&kh[off] = hi;
                        *(uint32_t*)&kl[off] = lo;
                    } else {
                        const size_t off = (((size_t)bb * NG_ + (hidx - NH_ - NG_)) * SQ_ + s) * HD_ + d;
                        *(uint32_t*)&vh[off] = pack_h2(__float2half(x0), __float2half(x1));
                    }
                }
            }
        }
    }
}

// ---------------------------------------------------------------------------
// Tensor-core flash attention (unchanged from R6)
// S-path: 3-term (QhKh + QlKh + QhKl). PV-path: 2-term ((Ph+Pl)·Vh).
// ---------------------------------------------------------------------------
#define FBM 128
#define FBN 64
#define KV_TILE_B (FBN*256)
#define FB_BUF    (3*KV_TILE_B)
#define FLASH2_SMEM (2*FB_BUF)

#define SWZ(row, gr) ((uint32_t)((row)*256 + ((((uint32_t)(gr)) ^ ((row)&7)) << 4)))

__global__ __launch_bounds__(256, 1)
void flash_mma_kernel(const __half* __restrict__ Qh, const __half* __restrict__ Ql,
                      const __half* __restrict__ Kh, const __half* __restrict__ Kl,
                      const __half* __restrict__ Vh,
                      __half* __restrict__ As)
{
    extern __shared__ char dsm[];
    const uint32_t sb = smem_u32(dsm);

    const int qb = gridDim.x - 1 - blockIdx.x;
    const int h  = blockIdx.y;
    const int b  = blockIdx.z;
    const int g  = h / REP_;

    const int tid  = threadIdx.x;
    const int lane = tid & 31;
    const int wid  = tid >> 5;
    const int q0   = qb * FBM;
    const int qrow = q0 + wid * 16;
    const int r1   = lane >> 2;
    const int c2   = (lane & 3) * 2;
    const int grp  = lane >> 3;
    const int ri   = lane & 7;

    const float scale = 0.08838834764831845f;

    const __half* Qhp = Qh + ((size_t)b * NH_ + h) * SQ_ * HD_;
    const __half* Qlp = Ql + ((size_t)b * NH_ + h) * SQ_ * HD_;
    const __half* Khp = Kh + ((size_t)b * NG_ + g) * SQ_ * HD_;
    const __half* Klp = Kl + ((size_t)b * NG_ + g) * SQ_ * HD_;
    const __half* Vhp = Vh + ((size_t)b * NG_ + g) * SQ_ * HD_;

    uint32_t qfh[8][4], qfl[8][4];
    #pragma unroll
    for (int kc = 0; kc < 8; kc++) {
        const int col = kc * 16 + c2;
        qfh[kc][0] = *(const uint32_t*)&Qhp[(size_t)(qrow + r1)     * HD_ + col];
        qfh[kc][1] = *(const uint32_t*)&Qhp[(size_t)(qrow + r1 + 8) * HD_ + col];
        qfh[kc][2] = *(const uint32_t*)&Qhp[(size_t)(qrow + r1)     * HD_ + col + 8];
        qfh[kc][3] = *(const uint32_t*)&Qhp[(size_t)(qrow + r1 + 8) * HD_ + col + 8];
        qfl[kc][0] = *(const uint32_t*)&Qlp[(size_t)(qrow + r1)     * HD_ + col];
        qfl[kc][1] = *(const uint32_t*)&Qlp[(size_t)(qrow + r1 + 8) * HD_ + col];
        qfl[kc][2] = *(const uint32_t*)&Qlp[(size_t)(qrow + r1)     * HD_ + col + 8];
        qfl[kc][3] = *(const uint32_t*)&Qlp[(size_t)(qrow + r1 + 8) * HD_ + col + 8];
    }

    float o[16][4];
    #pragma unroll
    for (int j = 0; j < 16; j++)
        #pragma unroll
        for (int e = 0; e < 4; e++) o[j][e] = 0.f;
    float m1 = -1e30f, m2 = -1e30f, l1 = 0.f, l2 = 0.f;

    auto issue_kv = [&](int jt, int buf) {
        const uint32_t bbase = sb + (uint32_t)buf * FB_BUF;
        const int s0 = jt * FBN;
        const __half* srcs[3] = {
            Khp + (size_t)s0 * HD_, Klp + (size_t)s0 * HD_,
            Vhp + (size_t)s0 * HD_ };
        #pragma unroll
        for (int t = 0; t < 3; t++) {
            #pragma unroll
            for (int i = 0; i < 4; i++) {
                const int gg = tid + i * 256;
                const int row = gg >> 4, c = gg & 15;
                cp_async16(bbase + t * KV_TILE_B + SWZ(row, c),
                           srcs[t] + (size_t)row * HD_ + c * 8);
            }
        }
        cp_commit();
    };

    const int njt = 2 * qb + 2;
    issue_kv(0, 0);

    for (int jt = 0; jt < njt; jt++) {
        if (jt + 1 < njt) { issue_kv(jt + 1, (jt + 1) & 1); cp_wait<1>(); }
        else              { cp_wait<0>(); }
        __syncthreads();

        const uint32_t bbase = sb + (uint32_t)(jt & 1) * FB_BUF;
        const uint32_t khb = bbase;
        const uint32_t klb = bbase + KV_TILE_B;
        const uint32_t vhb = bbase + 2 * KV_TILE_B;

        float s[8][4];
        #pragma unroll
        for (int j = 0; j < 8; j++)
            #pragma unroll
            for (int e = 0; e < 4; e++) s[j][e] = 0.f;

        #pragma unroll
        for (int kc = 0; kc < 8; kc++) {
            #pragma unroll
            for (int np = 0; np < 4; np++) {
                const int krow = np * 16 + ri + ((grp >> 1) << 3);
                const int kgr  = 2 * kc + (grp & 1);
                uint32_t h0,h1,h2,h3,l0,l1r,l2r,l3;
                ldm_x4(h0, h1, h2, h3, khb + SWZ(krow, kgr));
                ldm_x4(l0, l1r, l2r, l3, klb + SWZ(krow, kgr));
                mma_f16(s[2*np],   qfh[kc], h0, h1);
                mma_f16(s[2*np+1], qfh[kc], h2, h3);
                mma_f16(s[2*np],   qfl[kc], h0, h1);
                mma_f16(s[2*np+1], qfl[kc], h2, h3);
                mma_f16(s[2*np],   qfh[kc], l0, l1r);
                mma_f16(s[2*np+1], qfh[kc], l2r, l3);
            }
        }

        #pragma unroll
        for (int j = 0; j < 8; j++)
            #pragma unroll
            for (int e = 0; e < 4; e++) s[j][e] *= scale;

        if (jt >= 2 * qb) {
            const int row1 = qrow + r1, row2 = row1 + 8;
            #pragma unroll
            for (int j = 0; j < 8; j++) {
                const int col = jt * FBN + j * 8 + c2;
                if (col     > row1) s[j][0] = -1e30f;
                if (col + 1 > row1) s[j][1] = -1e30f;
                if (col     > row2) s[j][2] = -1e30f;
                if (col + 1 > row2) s[j][3] = -1e30f;
            }
        }

        float mx1 = -1e30f, mx2 = -1e30f;
        #pragma unroll
        for (int j = 0; j < 8; j++) {
            mx1 = fmaxf(mx1, fmaxf(s[j][0], s[j][1]));
            mx2 = fmaxf(mx2, fmaxf(s[j][2], s[j][3]));
        }
        mx1 = fmaxf(mx1, __shfl_xor_sync(0xffffffffu, mx1, 1));
        mx1 = fmaxf(mx1, __shfl_xor_sync(0xffffffffu, mx1, 2));
        mx2 = fmaxf(mx2, __shfl_xor_sync(0xffffffffu, mx2, 1));
        mx2 = fmaxf(mx2, __shfl_xor_sync(0xffffffffu, mx2, 2));

        const float mn1 = fmaxf(m1, mx1), mn2 = fmaxf(m2, mx2);
        const float a1 = __expf(m1 - mn1), a2 = __expf(m2 - mn2);
        m1 = mn1; m2 = mn2;

        float sum1 = 0.f, sum2 = 0.f;
        #pragma unroll
        for (int j = 0; j < 8; j++) {
            s[j][0] = __expf(s[j][0] - mn1);
            s[j][1] = __expf(s[j][1] - mn1);
            s[j][2] = __expf(s[j][2] - mn2);
            s[j][3] = __expf(s[j][3] - mn2);
            sum1 += s[j][0] + s[j][1];
            sum2 += s[j][2] + s[j][3];
        }
        sum1 += __shfl_xor_sync(0xffffffffu, sum1, 1);
        sum1 += __shfl_xor_sync(0xffffffffu, sum1, 2);
        sum2 += __shfl_xor_sync(0xffffffffu, sum2, 1);
        sum2 += __shfl_xor_sync(0xffffffffu, sum2, 2);
        l1 = l1 * a1 + sum1;
        l2 = l2 * a2 + sum2;

        #pragma unroll
        for (int j = 0; j < 16; j++) {
            o[j][0] *= a1; o[j][1] *= a1;
            o[j][2] *= a2; o[j][3] *= a2;
        }

        #pragma unroll
        for (int t = 0; t < 4; t++) {
            uint32_t ph[4], pl[4];
            split_pack(ph[0], pl[0], s[2*t][0],   s[2*t][1]);
            split_pack(ph[1], pl[1], s[2*t][2],   s[2*t][3]);
            split_pack(ph[2], pl[2], s[2*t+1][0], s[2*t+1][1]);
            split_pack(ph[3], pl[3], s[2*t+1][2], s[2*t+1][3]);
            #pragma unroll
            for (int np = 0; np < 8; np++) {
                const int vrow = t * 16 + ri + ((grp & 1) << 3);
                const int vgr  = 2 * np + (grp >> 1);
                uint32_t h0,h1,h2,h3;
                ldm_x4_t(h0, h1, h2, h3, vhb + SWZ(vrow, vgr));
                mma_f16(o[2*np],   ph, h0, h1);
                mma_f16(o[2*np+1], ph, h2, h3);
                mma_f16(o[2*np],   pl, h0, h1);
                mma_f16(o[2*np+1], pl, h2, h3);
            }
        }
        __syncthreads();
    }

    const float inv1 = 1.f / l1, inv2 = 1.f / l2;
    const size_t mr1 = (size_t)b * SQ_ + qrow + r1;
    const size_t mr2 = mr1 + 8;
    #pragma unroll
    for (int j = 0; j < 16; j++) {
        const int col = h * HD_ + j * 8 + c2;
        uint32_t hi, lo;
        split_pack(hi, lo, o[j][0] * inv1, o[j][1] * inv1);
        *(uint32_t*)&As[mr1 * KSPLIT_ + col]      = hi;
        *(uint32_t*)&As[mr1 * KSPLIT_ + H_ + col] = lo;
        split_pack(hi, lo, o[j][2] * inv2, o[j][3] * inv2);
        *(uint32_t*)&As[mr2 * KSPLIT_ + col]      = hi;
        *(uint32_t*)&As[mr2 * KSPLIT_ + H_ + col] = lo;
    }
}

// ---------------------------------------------------------------------------
// Launch
// ---------------------------------------------------------------------------
extern "C" void kernel_launch(void* const* d_in, const int* in_sizes, int n_in,
                              void* d_out, int out_size)
{
    const float* hidden = (const float*)d_in[0];
    const float* rope   = (const float*)d_in[1];
    const float* Wqkv   = (const float*)d_in[2];
    const float* bqkv   = (const float*)d_in[3];
    const float* Wd     = (const float*)d_in[4];
    float* out = (float*)d_out;

    __half *as, *bs, *qh, *ql, *kh, *kl, *vh;
    cudaGetSymbolAddress((void**)&as, g_as);
    cudaGetSymbolAddress((void**)&bs, g_bs);
    cudaGetSymbolAddress((void**)&qh, g_qh);
    cudaGetSymbolAddress((void**)&ql, g_ql);
    cudaGetSymbolAddress((void**)&kh, g_kh);
    cudaGetSymbolAddress((void**)&kl, g_kl);
    cudaGetSymbolAddress((void**)&vh, g_vh);

    cudaFuncSetAttribute(mma_gemm_kernel<0>,
                         cudaFuncAttributeMaxDynamicSharedMemorySize, GEMM_SMEM_BYTES);
    cudaFuncSetAttribute(mma_gemm_kernel<1>,
                         cudaFuncAttributeMaxDynamicSharedMemorySize, GEMM_SMEM_BYTES);
    cudaFuncSetAttribute(flash_mma_kernel,
                         cudaFuncAttributeMaxDynamicSharedMemorySize, FLASH2_SMEM);

    const size_t n8 = (size_t)MM_ * H_ / 8;

    // 1) split hidden -> As [M, 2K]; transpose+split Wqkv -> Bs [4608, 2K]
    split_a_kernel<<<(unsigned)((n8 + 255) / 256), 256>>>(hidden, as, H_, n8);
    transpose_split_kernel<<<dim3(QKV_OUT_ / 32, H_ / 32), 256>>>(Wqkv, bs, H_, QKV_OUT_);

    // 2) QKV GEMM with fused bias + RoPE + split + scatter
    mma_gemm_kernel<1><<<dim3(QKV_OUT_ / GBN, MM_ / GBM), 256, GEMM_SMEM_BYTES>>>(
        as, bs, bqkv, rope, nullptr, qh, ql, kh, kl, vh, QKV_OUT_, KSPLIT_);

    // 3) tensor-core flash attention -> writes split-As directly
    flash_mma_kernel<<<dim3(SQ_ / FBM, NH_, B_), 256, FLASH2_SMEM>>>(
        qh, ql, kh, kl, vh, as);

    // 4) transpose+split Wd -> Bs [4096, 2K]
    transpose_split_kernel<<<dim3(H_ / 32, H_ / 32), 256>>>(Wd, bs, H_, H_);

    // 5) out = ctx @ Wd
    mma_gemm_kernel<0><<<dim3(H_ / GBN, MM_ / GBM), 256, GEMM_SMEM_BYTES>>>(
        as, bs, nullptr, nullptr, out, nullptr, nullptr, nullptr, nullptr, nullptr,
        H_, KSPLIT_);
}

// round 8
// speedup vs baseline: 4.4594x; 1.1018x over previous
#include <cuda_runtime.h>
#include <cuda_fp16.h>
#include <cstdint>
#include <math.h>

// ---------------------------------------------------------------------------
// Problem constants
// ---------------------------------------------------------------------------
#define B_     2
#define SQ_    2048
#define H_     4096
#define NH_    32
#define HD_    128
#define NG_    2
#define QKV_OUT_ (NH_*HD_ + 2*NG_*HD_)   // 4608
#define Q_SZ_    (NH_*HD_)               // 4096
#define KV_SZ_   (NG_*HD_)               // 256
#define REP_     (NH_/NG_)               // 16
#define MM_      (B_*SQ_)                // 4096
#define KSPLIT_  (2*H_)                  // 8192 (A-side hi|lo layout)

// ---------------------------------------------------------------------------
// Scratch
// ---------------------------------------------------------------------------
__device__ __half g_as[(size_t)MM_*KSPLIT_];        // A: [hi | lo] over 2K
__device__ __half g_bs[(size_t)QKV_OUT_*H_];        // B: hi only, [N, K]
__device__ __half g_qh[(size_t)B_*NH_*SQ_*HD_];
__device__ __half g_ql[(size_t)B_*NH_*SQ_*HD_];
__device__ __half g_kh[(size_t)B_*NG_*SQ_*HD_];
__device__ __half g_kl[(size_t)B_*NG_*SQ_*HD_];
__device__ __half g_vh[(size_t)B_*NG_*SQ_*HD_];

// ---------------------------------------------------------------------------
// Helpers
// ---------------------------------------------------------------------------
__device__ __forceinline__ uint32_t smem_u32(const void* p) {
    uint32_t a;
    asm("{ .reg .u64 t; cvta.to.shared.u64 t, %1; cvt.u32.u64 %0, t; }" : "=r"(a) : "l"(p));
    return a;
}
__device__ __forceinline__ void cp_async16(uint32_t dst, const void* src) {
    asm volatile("cp.async.cg.shared.global [%0], [%1], 16;" :: "r"(dst), "l"(src));
}
__device__ __forceinline__ void cp_commit() {
    asm volatile("cp.async.commit_group;");
}
template<int N>
__device__ __forceinline__ void cp_wait() {
    asm volatile("cp.async.wait_group %0;" :: "n"(N));
}
__device__ __forceinline__ void ldm_x4(uint32_t& r0, uint32_t& r1, uint32_t& r2,
                                       uint32_t& r3, uint32_t addr) {
    asm volatile("ldmatrix.sync.aligned.m8n8.x4.shared.b16 {%0,%1,%2,%3}, [%4];"
                 : "=r"(r0), "=r"(r1), "=r"(r2), "=r"(r3) : "r"(addr));
}
__device__ __forceinline__ void ldm_x4_t(uint32_t& r0, uint32_t& r1, uint32_t& r2,
                                         uint32_t& r3, uint32_t addr) {
    asm volatile("ldmatrix.sync.aligned.m8n8.x4.trans.shared.b16 {%0,%1,%2,%3}, [%4];"
                 : "=r"(r0), "=r"(r1), "=r"(r2), "=r"(r3) : "r"(addr));
}
__device__ __forceinline__ void mma_f16(float* d, const uint32_t* a,
                                        uint32_t b0, uint32_t b1) {
    asm volatile(
        "mma.sync.aligned.m16n8k16.row.col.f32.f16.f16.f32 "
        "{%0,%1,%2,%3}, {%4,%5,%6,%7}, {%8,%9}, {%0,%1,%2,%3};"
        : "+f"(d[0]), "+f"(d[1]), "+f"(d[2]), "+f"(d[3])
        : "r"(a[0]), "r"(a[1]), "r"(a[2]), "r"(a[3]), "r"(b0), "r"(b1));
}
__device__ __forceinline__ uint32_t pack_h2(__half a, __half b) {
    return (uint32_t)__half_as_ushort(a) | ((uint32_t)__half_as_ushort(b) << 16);
}
__device__ __forceinline__ void split_pack(uint32_t& hi, uint32_t& lo, float p0, float p1) {
    __half h0 = __float2half(p0), h1 = __float2half(p1);
    __half e0 = __float2half(p0 - __half2float(h0));
    __half e1 = __float2half(p1 - __half2float(h1));
    hi = pack_h2(h0, h1);
    lo = pack_h2(e0, e1);
}

// ---------------------------------------------------------------------------
// fp32 -> fp16 split kernels
// ---------------------------------------------------------------------------
// A[M,K] fp32 -> As[M, 2K] fp16, segments [hi | lo]
__global__ __launch_bounds__(256)
void split_a_kernel(const float* __restrict__ A, __half* __restrict__ As,
                    int K, size_t n8)
{
    size_t g = (size_t)blockIdx.x * 256 + threadIdx.x;
    if (g >= n8) return;
    const int kpr = K / 8;
    const size_t m  = g / kpr;
    const int   k8  = (int)(g % kpr) * 8;
    float4 a0 = *(const float4*)&A[m * K + k8];
    float4 a1 = *(const float4*)&A[m * K + k8 + 4];
    float v[8] = {a0.x,a0.y,a0.z,a0.w,a1.x,a1.y,a1.z,a1.w};
    uint32_t hseg[4], lseg[4];
    #pragma unroll
    for (int j = 0; j < 4; j++) {
        __half h0 = __float2half(v[2*j]);
        __half h1 = __float2half(v[2*j+1]);
        hseg[j] = pack_h2(h0, h1);
        lseg[j] = pack_h2(__float2half(v[2*j]   - __half2float(h0)),
                          __float2half(v[2*j+1] - __half2float(h1)));
    }
    __half* row = As + m * (size_t)(2*K);
    *(uint4*)&row[k8]     = *(uint4*)hseg;
    *(uint4*)&row[K + k8] = *(uint4*)lseg;
}

// W[K,N] fp32 -> Bs[N, K] fp16 hi (transposed)
__global__ __launch_bounds__(256)
void transpose_h_kernel(const float* __restrict__ W, __half* __restrict__ Bs,
                        int K, int N)
{
    __shared__ float t[32][33];
    const int n0 = blockIdx.x * 32, k0 = blockIdx.y * 32;
    const int tx = threadIdx.x & 31, ty = threadIdx.x >> 5;
    #pragma unroll
    for (int i = 0; i < 4; i++)
        t[ty + 8*i][tx] = W[(size_t)(k0 + ty + 8*i) * N + n0 + tx];
    __syncthreads();
    #pragma unroll
    for (int i = 0; i < 4; i++) {
        float v = t[tx][ty + 8*i];
        Bs[(size_t)(n0 + ty + 8*i) * K + k0 + tx] = __float2half(v);
    }
}

// ---------------------------------------------------------------------------
// Dual-A fp16 GEMM: C[M,N] = (Ah + Al)[M,K] @ Bh[N,K]^T, K = 4096.
// Per k-chunk: load Ah, Al, Bh tiles; both A sets accumulate into same acc.
// MODE 0: fp32 C. MODE 1: fused bias+RoPE+split+scatter (QKV).
// ---------------------------------------------------------------------------
#define GBM 128
#define GBN 128
#define GBK 32
#define GLD 40
#define TILE_BYTES  (GBM*GLD*2)              // 10240 per tile
#define STG_BYTES   (3*TILE_BYTES)           // Ah, Al, B = 30720
#define GSTAGES 3
#define GEMM_SMEM_BYTES (GSTAGES*STG_BYTES)  // 92160

template<int MODE>
__global__ __launch_bounds__(256)
void mma_gemm_kernel(const __half* __restrict__ Ag,
                     const __half* __restrict__ Bg,
                     const float* __restrict__ bias,
                     const float* __restrict__ cache,
                     float* __restrict__ C,
                     __half* __restrict__ qh, __half* __restrict__ ql,
                     __half* __restrict__ kh, __half* __restrict__ kl,
                     __half* __restrict__ vh,
                     int N, int K)
{
    extern __shared__ char dsm[];
    const uint32_t sbase = smem_u32(dsm);

    const int tid  = threadIdx.x;
    const int lane = tid & 31;
    const int wid  = tid >> 5;
    const int wm   = wid >> 2;
    const int wn   = wid & 3;
    const int m0   = blockIdx.y * GBM;
    const int n0   = blockIdx.x * GBN;

    // A rows have stride 2K ([hi | lo]); B rows stride K.
    const __half* Ahr = Ag + (size_t)m0 * (2*K);
    const __half* Alr = Ahr + K;
    const __half* Brow = Bg + (size_t)n0 * K;

    const int NIT = K / GBK;    // 128

    auto issue_stage = [&](int kt, int slot) {
        const uint32_t st = sbase + slot * STG_BYTES;
        const int kO = kt * GBK;
        // 512 granules per tile, 2 per thread per tile
        #pragma unroll
        for (int h = 0; h < 2; h++) {
            const int g = tid + h * 256;
            const int r = g >> 2, c = g & 3;
            const uint32_t doff = (r * GLD + c * 8) * 2;
            cp_async16(st + doff,                 Ahr + (size_t)r * (2*K) + kO + c * 8);
            cp_async16(st + TILE_BYTES + doff,    Alr + (size_t)r * (2*K) + kO + c * 8);
            cp_async16(st + 2*TILE_BYTES + doff,  Brow + (size_t)r * K + kO + c * 8);
        }
        cp_commit();
    };

    float acc[4][4][4];
    #pragma unroll
    for (int i = 0; i < 4; i++)
        #pragma unroll
        for (int j = 0; j < 4; j++)
            #pragma unroll
            for (int r = 0; r < 4; r++) acc[i][j][r] = 0.f;

    issue_stage(0, 0);
    issue_stage(1, 1);

    const int a_r = lane & 15;
    const int a_c = (lane >> 4) << 3;
    const int b_r = (lane & 7) + ((lane >> 4) << 3);
    const int b_c = ((lane >> 3) & 1) << 3;

    for (int kt = 0; kt < NIT; kt++) {
        cp_wait<1>();
        __syncthreads();
        if (kt + 2 < NIT) issue_stage(kt + 2, (kt + 2) % GSTAGES);
        else cp_commit();

        const uint32_t st = sbase + (kt % GSTAGES) * STG_BYTES;
        const uint32_t sah = st;
        const uint32_t sal = st + TILE_BYTES;
        const uint32_t sb  = st + 2*TILE_BYTES;

        #pragma unroll
        for (int ks = 0; ks < 2; ks++) {
            const int kb = ks * 16;
            uint32_t ah[4][4], al[4][4];
            #pragma unroll
            for (int i = 0; i < 4; i++) {
                const uint32_t ro = ((wm*64 + i*16 + a_r) * GLD + kb + a_c) * 2;
                ldm_x4(ah[i][0], ah[i][1], ah[i][2], ah[i][3], sah + ro);
                ldm_x4(al[i][0], al[i][1], al[i][2], al[i][3], sal + ro);
            }
            uint32_t b[4][2];
            #pragma unroll
            for (int j = 0; j < 2; j++) {
                uint32_t r0, r1, r2, r3;
                ldm_x4(r0, r1, r2, r3,
                       sb + ((wn*32 + j*16 + b_r) * GLD + kb + b_c) * 2);
                b[j*2][0]   = r0; b[j*2][1]   = r1;
                b[j*2+1][0] = r2; b[j*2+1][1] = r3;
            }
            #pragma unroll
            for (int i = 0; i < 4; i++)
                #pragma unroll
                for (int j = 0; j < 4; j++) {
                    mma_f16(acc[i][j], ah[i], b[j][0], b[j][1]);
                    mma_f16(acc[i][j], al[i], b[j][0], b[j][1]);
                }
        }
    }

    const int cr = lane >> 2;
    const int cc = (lane & 3) * 2;

    if (MODE == 0) {
        #pragma unroll
        for (int j = 0; j < 4; j++) {
            const int col = n0 + wn*32 + j*8 + cc;
            #pragma unroll
            for (int i = 0; i < 4; i++) {
                const int row = m0 + wm*64 + i*16 + cr;
                *(float2*)&C[(size_t)row * N + col] =
                    make_float2(acc[i][j][0], acc[i][j][1]);
                *(float2*)&C[(size_t)(row + 8) * N + col] =
                    make_float2(acc[i][j][2], acc[i][j][3]);
            }
        }
    } else {
        // Fused bias + RoPE + split + scatter. One head per CTA col-block.
        const int hidx = n0 >> 7;            // 0..35
        #pragma unroll
        for (int j = 0; j < 4; j++) {
            const int d   = wn*32 + j*8 + cc;         // 0..126 (even), within head
            const float2 bv = *(const float2*)&bias[n0 + d];
            const bool rot = (d < 64);
            const int p = d >> 1;
            #pragma unroll
            for (int i = 0; i < 4; i++) {
                #pragma unroll
                for (int hrw = 0; hrw < 2; hrw++) {
                    const int row = m0 + wm*64 + i*16 + cr + hrw*8;
                    float x0 = acc[i][j][hrw*2+0] + bv.x;
                    float x1 = acc[i][j][hrw*2+1] + bv.y;
                    const int bb = row >> 11;          // /SQ_
                    const int s  = row & (SQ_ - 1);
                    if (hidx < NH_ + NG_ && rot) {
                        const float2 c = *(const float2*)&cache[((size_t)s * 32 + p) * 2];
                        const float o0 = x0 * c.x - x1 * c.y;
                        const float o1 = x1 * c.x + x0 * c.y;
                        x0 = o0; x1 = o1;
                    }
                    uint32_t hi, lo;
                    if (hidx < NH_) {
                        split_pack(hi, lo, x0, x1);
                        const size_t off = (((size_t)bb * NH_ + hidx) * SQ_ + s) * HD_ + d;
                        *(uint32_t*)&qh[off] = hi;
                        *(uint32_t*)&ql[off] = lo;
                    } else if (hidx < NH_ + NG_) {
                        split_pack(hi, lo, x0, x1);
                        const size_t off = (((size_t)bb * NG_ + (hidx - NH_)) * SQ_ + s) * HD_ + d;
                        *(uint32_t*)&kh[off] = hi;
                        *(uint32_t*)&kl[off] = lo;
                    } else {
                        const size_t off = (((size_t)bb * NG_ + (hidx - NH_ - NG_)) * SQ_ + s) * HD_ + d;
                        *(uint32_t*)&vh[off] = pack_h2(__float2half(x0), __float2half(x1));
                    }
                }
            }
        }
    }
}

// ---------------------------------------------------------------------------
// Tensor-core flash attention (unchanged from R6/R7)
// S-path: 3-term (QhKh + QlKh + QhKl). PV-path: 2-term ((Ph+Pl)·Vh).
// ---------------------------------------------------------------------------
#define FBM 128
#define FBN 64
#define KV_TILE_B (FBN*256)
#define FB_BUF    (3*KV_TILE_B)
#define FLASH2_SMEM (2*FB_BUF)

#define SWZ(row, gr) ((uint32_t)((row)*256 + ((((uint32_t)(gr)) ^ ((row)&7)) << 4)))

__global__ __launch_bounds__(256, 1)
void flash_mma_kernel(const __half* __restrict__ Qh, const __half* __restrict__ Ql,
                      const __half* __restrict__ Kh, const __half* __restrict__ Kl,
                      const __half* __restrict__ Vh,
                      __half* __restrict__ As)
{
    extern __shared__ char dsm[];
    const uint32_t sb = smem_u32(dsm);

    const int qb = gridDim.x - 1 - blockIdx.x;
    const int h  = blockIdx.y;
    const int b  = blockIdx.z;
    const int g  = h / REP_;

    const int tid  = threadIdx.x;
    const int lane = tid & 31;
    const int wid  = tid >> 5;
    const int q0   = qb * FBM;
    const int qrow = q0 + wid * 16;
    const int r1   = lane >> 2;
    const int c2   = (lane & 3) * 2;
    const int grp  = lane >> 3;
    const int ri   = lane & 7;

    const float scale = 0.08838834764831845f;

    const __half* Qhp = Qh + ((size_t)b * NH_ + h) * SQ_ * HD_;
    const __half* Qlp = Ql + ((size_t)b * NH_ + h) * SQ_ * HD_;
    const __half* Khp = Kh + ((size_t)b * NG_ + g) * SQ_ * HD_;
    const __half* Klp = Kl + ((size_t)b * NG_ + g) * SQ_ * HD_;
    const __half* Vhp = Vh + ((size_t)b * NG_ + g) * SQ_ * HD_;

    uint32_t qfh[8][4], qfl[8][4];
    #pragma unroll
    for (int kc = 0; kc < 8; kc++) {
        const int col = kc * 16 + c2;
        qfh[kc][0] = *(const uint32_t*)&Qhp[(size_t)(qrow + r1)     * HD_ + col];
        qfh[kc][1] = *(const uint32_t*)&Qhp[(size_t)(qrow + r1 + 8) * HD_ + col];
        qfh[kc][2] = *(const uint32_t*)&Qhp[(size_t)(qrow + r1)     * HD_ + col + 8];
        qfh[kc][3] = *(const uint32_t*)&Qhp[(size_t)(qrow + r1 + 8) * HD_ + col + 8];
        qfl[kc][0] = *(const uint32_t*)&Qlp[(size_t)(qrow + r1)     * HD_ + col];
        qfl[kc][1] = *(const uint32_t*)&Qlp[(size_t)(qrow + r1 + 8) * HD_ + col];
        qfl[kc][2] = *(const uint32_t*)&Qlp[(size_t)(qrow + r1)     * HD_ + col + 8];
        qfl[kc][3] = *(const uint32_t*)&Qlp[(size_t)(qrow + r1 + 8) * HD_ + col + 8];
    }

    float o[16][4];
    #pragma unroll
    for (int j = 0; j < 16; j++)
        #pragma unroll
        for (int e = 0; e < 4; e++) o[j][e] = 0.f;
    float m1 = -1e30f, m2 = -1e30f, l1 = 0.f, l2 = 0.f;

    auto issue_kv = [&](int jt, int buf) {
        const uint32_t bbase = sb + (uint32_t)buf * FB_BUF;
        const int s0 = jt * FBN;
        const __half* srcs[3] = {
            Khp + (size_t)s0 * HD_, Klp + (size_t)s0 * HD_,
            Vhp + (size_t)s0 * HD_ };
        #pragma unroll
        for (int t = 0; t < 3; t++) {
            #pragma unroll
            for (int i = 0; i < 4; i++) {
                const int gg = tid + i * 256;
                const int row = gg >> 4, c = gg & 15;
                cp_async16(bbase + t * KV_TILE_B + SWZ(row, c),
                           srcs[t] + (size_t)row * HD_ + c * 8);
            }
        }
        cp_commit();
    };

    const int njt = 2 * qb + 2;
    issue_kv(0, 0);

    for (int jt = 0; jt < njt; jt++) {
        if (jt + 1 < njt) { issue_kv(jt + 1, (jt + 1) & 1); cp_wait<1>(); }
        else              { cp_wait<0>(); }
        __syncthreads();

        const uint32_t bbase = sb + (uint32_t)(jt & 1) * FB_BUF;
        const uint32_t khb = bbase;
        const uint32_t klb = bbase + KV_TILE_B;
        const uint32_t vhb = bbase + 2 * KV_TILE_B;

        float s[8][4];
        #pragma unroll
        for (int j = 0; j < 8; j++)
            #pragma unroll
            for (int e = 0; e < 4; e++) s[j][e] = 0.f;

        #pragma unroll
        for (int kc = 0; kc < 8; kc++) {
            #pragma unroll
            for (int np = 0; np < 4; np++) {
                const int krow = np * 16 + ri + ((grp >> 1) << 3);
                const int kgr  = 2 * kc + (grp & 1);
                uint32_t h0,h1,h2,h3,l0,l1r,l2r,l3;
                ldm_x4(h0, h1, h2, h3, khb + SWZ(krow, kgr));
                ldm_x4(l0, l1r, l2r, l3, klb + SWZ(krow, kgr));
                mma_f16(s[2*np],   qfh[kc], h0, h1);
                mma_f16(s[2*np+1], qfh[kc], h2, h3);
                mma_f16(s[2*np],   qfl[kc], h0, h1);
                mma_f16(s[2*np+1], qfl[kc], h2, h3);
                mma_f16(s[2*np],   qfh[kc], l0, l1r);
                mma_f16(s[2*np+1], qfh[kc], l2r, l3);
            }
        }

        #pragma unroll
        for (int j = 0; j < 8; j++)
            #pragma unroll
            for (int e = 0; e < 4; e++) s[j][e] *= scale;

        if (jt >= 2 * qb) {
            const int row1 = qrow + r1, row2 = row1 + 8;
            #pragma unroll
            for (int j = 0; j < 8; j++) {
                const int col = jt * FBN + j * 8 + c2;
                if (col     > row1) s[j][0] = -1e30f;
                if (col + 1 > row1) s[j][1] = -1e30f;
                if (col     > row2) s[j][2] = -1e30f;
                if (col + 1 > row2) s[j][3] = -1e30f;
            }
        }

        float mx1 = -1e30f, mx2 = -1e30f;
        #pragma unroll
        for (int j = 0; j < 8; j++) {
            mx1 = fmaxf(mx1, fmaxf(s[j][0], s[j][1]));
            mx2 = fmaxf(mx2, fmaxf(s[j][2], s[j][3]));
        }
        mx1 = fmaxf(mx1, __shfl_xor_sync(0xffffffffu, mx1, 1));
        mx1 = fmaxf(mx1, __shfl_xor_sync(0xffffffffu, mx1, 2));
        mx2 = fmaxf(mx2, __shfl_xor_sync(0xffffffffu, mx2, 1));
        mx2 = fmaxf(mx2, __shfl_xor_sync(0xffffffffu, mx2, 2));

        const float mn1 = fmaxf(m1, mx1), mn2 = fmaxf(m2, mx2);
        const float a1 = __expf(m1 - mn1), a2 = __expf(m2 - mn2);
        m1 = mn1; m2 = mn2;

        float sum1 = 0.f, sum2 = 0.f;
        #pragma unroll
        for (int j = 0; j < 8; j++) {
            s[j][0] = __expf(s[j][0] - mn1);
            s[j][1] = __expf(s[j][1] - mn1);
            s[j][2] = __expf(s[j][2] - mn2);
            s[j][3] = __expf(s[j][3] - mn2);
            sum1 += s[j][0] + s[j][1];
            sum2 += s[j][2] + s[j][3];
        }
        sum1 += __shfl_xor_sync(0xffffffffu, sum1, 1);
        sum1 += __shfl_xor_sync(0xffffffffu, sum1, 2);
        sum2 += __shfl_xor_sync(0xffffffffu, sum2, 1);
        sum2 += __shfl_xor_sync(0xffffffffu, sum2, 2);
        l1 = l1 * a1 + sum1;
        l2 = l2 * a2 + sum2;

        #pragma unroll
        for (int j = 0; j < 16; j++) {
            o[j][0] *= a1; o[j][1] *= a1;
            o[j][2] *= a2; o[j][3] *= a2;
        }

        #pragma unroll
        for (int t = 0; t < 4; t++) {
            uint32_t ph[4], pl[4];
            split_pack(ph[0], pl[0], s[2*t][0],   s[2*t][1]);
            split_pack(ph[1], pl[1], s[2*t][2],   s[2*t][3]);
            split_pack(ph[2], pl[2], s[2*t+1][0], s[2*t+1][1]);
            split_pack(ph[3], pl[3], s[2*t+1][2], s[2*t+1][3]);
            #pragma unroll
            for (int np = 0; np < 8; np++) {
                const int vrow = t * 16 + ri + ((grp & 1) << 3);
                const int vgr  = 2 * np + (grp >> 1);
                uint32_t h0,h1,h2,h3;
                ldm_x4_t(h0, h1, h2, h3, vhb + SWZ(vrow, vgr));
                mma_f16(o[2*np],   ph, h0, h1);
                mma_f16(o[2*np+1], ph, h2, h3);
                mma_f16(o[2*np],   pl, h0, h1);
                mma_f16(o[2*np+1], pl, h2, h3);
            }
        }
        __syncthreads();
    }

    const float inv1 = 1.f / l1, inv2 = 1.f / l2;
    const size_t mr1 = (size_t)b * SQ_ + qrow + r1;
    const size_t mr2 = mr1 + 8;
    #pragma unroll
    for (int j = 0; j < 16; j++) {
        const int col = h * HD_ + j * 8 + c2;
        uint32_t hi, lo;
        split_pack(hi, lo, o[j][0] * inv1, o[j][1] * inv1);
        *(uint32_t*)&As[mr1 * KSPLIT_ + col]      = hi;
        *(uint32_t*)&As[mr1 * KSPLIT_ + H_ + col] = lo;
        split_pack(hi, lo, o[j][2] * inv2, o[j][3] * inv2);
        *(uint32_t*)&As[mr2 * KSPLIT_ + col]      = hi;
        *(uint32_t*)&As[mr2 * KSPLIT_ + H_ + col] = lo;
    }
}

// ---------------------------------------------------------------------------
// Launch
// ---------------------------------------------------------------------------
extern "C" void kernel_launch(void* const* d_in, const int* in_sizes, int n_in,
                              void* d_out, int out_size)
{
    const float* hidden = (const float*)d_in[0];
    const float* rope   = (const float*)d_in[1];
    const float* Wqkv   = (const float*)d_in[2];
    const float* bqkv   = (const float*)d_in[3];
    const float* Wd     = (const float*)d_in[4];
    float* out = (float*)d_out;

    __half *as, *bs, *qh, *ql, *kh, *kl, *vh;
    cudaGetSymbolAddress((void**)&as, g_as);
    cudaGetSymbolAddress((void**)&bs, g_bs);
    cudaGetSymbolAddress((void**)&qh, g_qh);
    cudaGetSymbolAddress((void**)&ql, g_ql);
    cudaGetSymbolAddress((void**)&kh, g_kh);
    cudaGetSymbolAddress((void**)&kl, g_kl);
    cudaGetSymbolAddress((void**)&vh, g_vh);

    cudaFuncSetAttribute(mma_gemm_kernel<0>,
                         cudaFuncAttributeMaxDynamicSharedMemorySize, GEMM_SMEM_BYTES);
    cudaFuncSetAttribute(mma_gemm_kernel<1>,
                         cudaFuncAttributeMaxDynamicSharedMemorySize, GEMM_SMEM_BYTES);
    cudaFuncSetAttribute(flash_mma_kernel,
                         cudaFuncAttributeMaxDynamicSharedMemorySize, FLASH2_SMEM);

    const size_t n8 = (size_t)MM_ * H_ / 8;

    // 1) split hidden -> As [M, 2K]; transpose Wqkv hi -> Bs [4608, 4096]
    split_a_kernel<<<(unsigned)((n8 + 255) / 256), 256>>>(hidden, as, H_, n8);
    transpose_h_kernel<<<dim3(QKV_OUT_ / 32, H_ / 32), 256>>>(Wqkv, bs, H_, QKV_OUT_);

    // 2) QKV GEMM (dual-A) with fused bias + RoPE + split + scatter
    mma_gemm_kernel<1><<<dim3(QKV_OUT_ / GBN, MM_ / GBM), 256, GEMM_SMEM_BYTES>>>(
        as, bs, bqkv, rope, nullptr, qh, ql, kh, kl, vh, QKV_OUT_, H_);

    // 3) tensor-core flash attention -> writes split-As directly
    flash_mma_kernel<<<dim3(SQ_ / FBM, NH_, B_), 256, FLASH2_SMEM>>>(
        qh, ql, kh, kl, vh, as);

    // 4) transpose Wd hi -> Bs [4096, 4096]
    transpose_h_kernel<<<dim3(H_ / 32, H_ / 32), 256>>>(Wd, bs, H_, H_);

    // 5) out = ctx @ Wd (dual-A)
    mma_gemm_kernel<0><<<dim3(H_ / GBN, MM_ / GBM), 256, GEMM_SMEM_BYTES>>>(
        as, bs, nullptr, nullptr, out, nullptr, nullptr, nullptr, nullptr, nullptr,
        H_, H_);
}